// round 1
// baseline (speedup 1.0000x reference)
#include <cuda_runtime.h>
#include <math.h>

// Problem constants
static constexpr int B = 2, S = 2048, D = 2048;
static constexpr int H = 16, KVH = 4, HD = 128;
static constexpr int MROWS = B * S;            // 4096
static constexpr int WINDOW = 512, GLOBALK = 64;
static constexpr float SCALE = 0.08838834764831845f;  // 1/sqrt(128)

// -------- scratch (device globals: allocation-free) --------
__device__ float g_q [(size_t)MROWS * (H * HD)];    // 4096 x 2048
__device__ float g_k [(size_t)MROWS * (KVH * HD)];  // 4096 x 512
__device__ float g_v [(size_t)MROWS * (KVH * HD)];  // 4096 x 512
__device__ float g_tmp[(size_t)MROWS * 128];        // 4096 x 128 (lora rank)
__device__ float g_ao[(size_t)MROWS * (H * HD)];    // attention output

// ============================================================
// GEMM: C[M,N] = A[M,K] @ B[N,K]^T   (optionally +=)
// 128x128 tile, BK=8, 256 threads, 8x8 per-thread micro-tile
// Requires: M%128==0, N%128==0, K%8==0
// ============================================================
template<bool ACCUM>
__global__ void __launch_bounds__(256) gemm_tn128(
    const float* __restrict__ A, const float* __restrict__ Bm,
    float* __restrict__ C, int M, int N, int K)
{
    __shared__ float As[8][128];
    __shared__ float Bs[8][128];
    const int bm = blockIdx.y * 128, bn = blockIdx.x * 128;
    const int tid = threadIdx.x;
    const int lr = tid >> 1;            // 0..127
    const int lc = (tid & 1) * 4;       // 0 or 4
    const int tx = tid & 15, ty = tid >> 4;

    float acc[8][8];
#pragma unroll
    for (int i = 0; i < 8; i++)
#pragma unroll
        for (int j = 0; j < 8; j++) acc[i][j] = 0.f;

    const float* Ap = A  + (size_t)(bm + lr) * K + lc;
    const float* Bp = Bm + (size_t)(bn + lr) * K + lc;

    for (int k0 = 0; k0 < K; k0 += 8) {
        float4 a4 = *(const float4*)(Ap + k0);
        float4 b4 = *(const float4*)(Bp + k0);
        __syncthreads();
        As[lc+0][lr] = a4.x; As[lc+1][lr] = a4.y;
        As[lc+2][lr] = a4.z; As[lc+3][lr] = a4.w;
        Bs[lc+0][lr] = b4.x; Bs[lc+1][lr] = b4.y;
        Bs[lc+2][lr] = b4.z; Bs[lc+3][lr] = b4.w;
        __syncthreads();
#pragma unroll
        for (int kk = 0; kk < 8; kk++) {
            float a[8], b[8];
            *(float4*)&a[0] = *(const float4*)&As[kk][ty*8];
            *(float4*)&a[4] = *(const float4*)&As[kk][ty*8+4];
            *(float4*)&b[0] = *(const float4*)&Bs[kk][tx*8];
            *(float4*)&b[4] = *(const float4*)&Bs[kk][tx*8+4];
#pragma unroll
            for (int i = 0; i < 8; i++)
#pragma unroll
                for (int j = 0; j < 8; j++)
                    acc[i][j] += a[i] * b[j];
        }
    }

#pragma unroll
    for (int i = 0; i < 8; i++) {
        float* cp = C + (size_t)(bm + ty*8 + i) * N + bn + tx*8;
#pragma unroll
        for (int j4 = 0; j4 < 2; j4++) {
            float4 r;
            r.x = acc[i][j4*4+0]; r.y = acc[i][j4*4+1];
            r.z = acc[i][j4*4+2]; r.w = acc[i][j4*4+3];
            if (ACCUM) {
                float4 o = *(const float4*)(cp + j4*4);
                r.x += o.x; r.y += o.y; r.z += o.z; r.w += o.w;
            }
            *(float4*)(cp + j4*4) = r;
        }
    }
}

// 64x64 tile variant for narrow-N GEMMs (N=128 -> 128 blocks instead of 32).
// Requires: M%64==0, N%64==0, K%16==0
template<bool ACCUM>
__global__ void __launch_bounds__(256) gemm_tn64(
    const float* __restrict__ A, const float* __restrict__ Bm,
    float* __restrict__ C, int M, int N, int K)
{
    __shared__ float As[16][64];
    __shared__ float Bs[16][64];
    const int bm = blockIdx.y * 64, bn = blockIdx.x * 64;
    const int tid = threadIdx.x;
    const int lr = tid >> 2;           // 0..63
    const int lc = (tid & 3) * 4;      // 0,4,8,12
    const int tx = tid & 15, ty = tid >> 4;

    float acc[4][4];
#pragma unroll
    for (int i = 0; i < 4; i++)
#pragma unroll
        for (int j = 0; j < 4; j++) acc[i][j] = 0.f;

    const float* Ap = A  + (size_t)(bm + lr) * K + lc;
    const float* Bp = Bm + (size_t)(bn + lr) * K + lc;

    for (int k0 = 0; k0 < K; k0 += 16) {
        float4 a4 = *(const float4*)(Ap + k0);
        float4 b4 = *(const float4*)(Bp + k0);
        __syncthreads();
        As[lc+0][lr] = a4.x; As[lc+1][lr] = a4.y;
        As[lc+2][lr] = a4.z; As[lc+3][lr] = a4.w;
        Bs[lc+0][lr] = b4.x; Bs[lc+1][lr] = b4.y;
        Bs[lc+2][lr] = b4.z; Bs[lc+3][lr] = b4.w;
        __syncthreads();
#pragma unroll
        for (int kk = 0; kk < 16; kk++) {
            float4 a = *(const float4*)&As[kk][ty*4];
            float4 b = *(const float4*)&Bs[kk][tx*4];
            acc[0][0] += a.x*b.x; acc[0][1] += a.x*b.y; acc[0][2] += a.x*b.z; acc[0][3] += a.x*b.w;
            acc[1][0] += a.y*b.x; acc[1][1] += a.y*b.y; acc[1][2] += a.y*b.z; acc[1][3] += a.y*b.w;
            acc[2][0] += a.z*b.x; acc[2][1] += a.z*b.y; acc[2][2] += a.z*b.z; acc[2][3] += a.z*b.w;
            acc[3][0] += a.w*b.x; acc[3][1] += a.w*b.y; acc[3][2] += a.w*b.z; acc[3][3] += a.w*b.w;
        }
    }

#pragma unroll
    for (int i = 0; i < 4; i++) {
        float* cp = C + (size_t)(bm + ty*4 + i) * N + bn + tx*4;
        float4 r;
        r.x = acc[i][0]; r.y = acc[i][1]; r.z = acc[i][2]; r.w = acc[i][3];
        if (ACCUM) {
            float4 o = *(const float4*)cp;
            r.x += o.x; r.y += o.y; r.z += o.z; r.w += o.w;
        }
        *(float4*)cp = r;
    }
}

// ============================================================
// RoPE (interleaved pairs), in place.  t: [B*S*heads][128]
// ============================================================
__global__ void rope_kernel(float* __restrict__ t, int heads, int total)
{
    int idx = blockIdx.x * 256 + threadIdx.x;
    if (idx >= total) return;
    int d   = idx & 63;
    int row = idx >> 6;
    int s   = (row / heads) & (S - 1);
    double invf = pow(1.0e6, -(double)d / 64.0);
    float ang = (float)s * (float)invf;
    float sn, cs;
    sincosf(ang, &sn, &cs);
    float* p = t + (size_t)row * 128 + 2 * d;
    float xr = p[0], xi = p[1];
    p[0] = xr * cs - xi * sn;
    p[1] = xr * sn + xi * cs;
}

// ============================================================
// Flash-style masked attention.
// Block: (q-block of 64 rows) x head x batch.  256 threads = 8 warps,
// each warp owns 8 query rows; key blocks of 64.
// allowed(i,j) = (j<=i) && ((i-j<512) || (j<64))
// Key blocks: {0} U [max(0,qb-8) .. qb]
// ============================================================
static constexpr int SMEM_ATTN = (64*128 + 64*132 + 64*128 + 64*64) * 4; // 115712 B

__global__ void __launch_bounds__(256) attn_kernel(
    const float* __restrict__ q, const float* __restrict__ k,
    const float* __restrict__ v, float* __restrict__ ao)
{
    extern __shared__ float sh[];
    float* Qs = sh;                  // [64][128]
    float* Ks = Qs + 64*128;         // [64][132] padded
    float* Vs = Ks + 64*132;         // [64][128]
    float* Ps = Vs + 64*128;         // [64][64]

    const int qb = blockIdx.x, h = blockIdx.y, b = blockIdx.z;
    const int i0 = qb * 64;
    const int tid = threadIdx.x, lane = tid & 31, warp = tid >> 5;
    const int kvh = h >> 2;   // H/KVH = 4

    // Load Q tile, pre-scaled by 1/sqrt(HD)
    for (int idx = tid; idx < 64*32; idx += 256) {
        int r = idx >> 5, c4 = idx & 31;
        float4 t = *(const float4*)&q[((size_t)(b*S + i0 + r)) * (H*HD) + h*HD + c4*4];
        t.x *= SCALE; t.y *= SCALE; t.z *= SCALE; t.w *= SCALE;
        *(float4*)&Qs[r*128 + c4*4] = t;
    }

    float m[8], l[8];
    float4 o[8];
#pragma unroll
    for (int rl = 0; rl < 8; rl++) {
        m[rl] = -1e30f; l[rl] = 0.f;
        o[rl].x = o[rl].y = o[rl].z = o[rl].w = 0.f;
    }

    int startb = qb - 8; if (startb < 0) startb = 0;
    const int extra = (startb > 0) ? 1 : 0;
    const int nblk = (qb - startb + 1) + extra;

    for (int bi = 0; bi < nblk; bi++) {
        const int kb = extra ? (bi == 0 ? 0 : startb + bi - 1) : (startb + bi);
        __syncthreads();   // previous block's compute done before overwriting K/V
        for (int idx = tid; idx < 64*32; idx += 256) {
            int r = idx >> 5, c4 = idx & 31;
            size_t gb = ((size_t)(b*S + kb*64 + r)) * (KVH*HD) + kvh*HD + c4*4;
            float4 kk4 = *(const float4*)&k[gb];
            float4 vv4 = *(const float4*)&v[gb];
            *(float4*)&Ks[r*132 + c4*4] = kk4;
            *(float4*)&Vs[r*128 + c4*4] = vv4;
        }
        __syncthreads();

#pragma unroll 1
        for (int rl = 0; rl < 8; rl++) {
            const int r = warp*8 + rl;
            const int i = i0 + r;
            // scores for keys j = kb*64 + lane, + lane+32
            float s0 = 0.f, s1 = 0.f;
            const float4* qrow = (const float4*)&Qs[r*128];
            const float4* kr0  = (const float4*)&Ks[lane*132];
            const float4* kr1  = (const float4*)&Ks[(lane+32)*132];
#pragma unroll
            for (int d = 0; d < 32; d++) {
                float4 qq = qrow[d];
                float4 ka = kr0[d];
                float4 kb4 = kr1[d];
                s0 += qq.x*ka.x  + qq.y*ka.y  + qq.z*ka.z  + qq.w*ka.w;
                s1 += qq.x*kb4.x + qq.y*kb4.y + qq.z*kb4.z + qq.w*kb4.w;
            }
            const int j0 = kb*64 + lane, j1 = j0 + 32;
            bool a0 = (j0 <= i) && (((i - j0) < WINDOW) || (j0 < GLOBALK));
            bool a1 = (j1 <= i) && (((i - j1) < WINDOW) || (j1 < GLOBALK));
            if (!a0) s0 = -1e30f;
            if (!a1) s1 = -1e30f;

            float smax = fmaxf(s0, s1);
#pragma unroll
            for (int off = 16; off; off >>= 1)
                smax = fmaxf(smax, __shfl_xor_sync(0xffffffffu, smax, off));
            float newm = fmaxf(m[rl], smax);
            float p0 = __expf(s0 - newm);
            float p1 = __expf(s1 - newm);
            float alpha = __expf(m[rl] - newm);
            float psum = p0 + p1;
#pragma unroll
            for (int off = 16; off; off >>= 1)
                psum += __shfl_xor_sync(0xffffffffu, psum, off);
            l[rl] = l[rl] * alpha + psum;
            o[rl].x *= alpha; o[rl].y *= alpha; o[rl].z *= alpha; o[rl].w *= alpha;
            m[rl] = newm;

            Ps[r*64 + lane]      = p0;
            Ps[r*64 + lane + 32] = p1;
            __syncwarp();

            const float* prow = &Ps[r*64];
#pragma unroll 8
            for (int j = 0; j < 64; j++) {
                float p = prow[j];
                float4 vv = *(const float4*)&Vs[j*128 + lane*4];
                o[rl].x += p * vv.x; o[rl].y += p * vv.y;
                o[rl].z += p * vv.z; o[rl].w += p * vv.w;
            }
        }
    }

    // epilogue: normalize and store
#pragma unroll
    for (int rl = 0; rl < 8; rl++) {
        const int r = warp*8 + rl;
        const int i = i0 + r;
        float inv = 1.f / l[rl];
        float4 t;
        t.x = o[rl].x * inv; t.y = o[rl].y * inv;
        t.z = o[rl].z * inv; t.w = o[rl].w * inv;
        *(float4*)&ao[((size_t)(b*S + i)) * (H*HD) + h*HD + lane*4] = t;
    }
}

// ============================================================
// Host side
// ============================================================
static inline void run_gemm(const float* A, const float* Bm, float* C,
                            int M, int N, int K, bool accum)
{
    if (N >= 256) {
        dim3 grid(N/128, M/128);
        if (accum) gemm_tn128<true ><<<grid, 256>>>(A, Bm, C, M, N, K);
        else       gemm_tn128<false><<<grid, 256>>>(A, Bm, C, M, N, K);
    } else {
        dim3 grid(N/64, M/64);
        if (accum) gemm_tn64<true ><<<grid, 256>>>(A, Bm, C, M, N, K);
        else       gemm_tn64<false><<<grid, 256>>>(A, Bm, C, M, N, K);
    }
}

extern "C" void kernel_launch(void* const* d_in, const int* in_sizes, int n_in,
                              void* d_out, int out_size)
{
    const float* x    = (const float*)d_in[0];
    const float* wq_w = (const float*)d_in[1];
    const float* wq_a = (const float*)d_in[2];
    const float* wq_b = (const float*)d_in[3];
    const float* wk_w = (const float*)d_in[4];
    const float* wk_a = (const float*)d_in[5];
    const float* wk_b = (const float*)d_in[6];
    const float* wv_w = (const float*)d_in[7];
    const float* wv_a = (const float*)d_in[8];
    const float* wv_b = (const float*)d_in[9];
    const float* wo_w = (const float*)d_in[10];
    const float* wo_a = (const float*)d_in[11];
    const float* wo_b = (const float*)d_in[12];
    float* out = (float*)d_out;

    float *q, *k, *v, *tmp, *ao;
    cudaGetSymbolAddress((void**)&q,   g_q);
    cudaGetSymbolAddress((void**)&k,   g_k);
    cudaGetSymbolAddress((void**)&v,   g_v);
    cudaGetSymbolAddress((void**)&tmp, g_tmp);
    cudaGetSymbolAddress((void**)&ao,  g_ao);

    cudaFuncSetAttribute(attn_kernel,
        cudaFuncAttributeMaxDynamicSharedMemorySize, SMEM_ATTN);

    const int M = MROWS;

    // Q = x @ wq_w^T + (x @ wq_a^T) @ wq_b^T
    run_gemm(x,   wq_w, q,   M, H*HD, D,   false);
    run_gemm(x,   wq_a, tmp, M, 128,  D,   false);
    run_gemm(tmp, wq_b, q,   M, H*HD, 128, true);
    // K
    run_gemm(x,   wk_w, k,   M, KVH*HD, D,   false);
    run_gemm(x,   wk_a, tmp, M, 128,    D,   false);
    run_gemm(tmp, wk_b, k,   M, KVH*HD, 128, true);
    // V
    run_gemm(x,   wv_w, v,   M, KVH*HD, D,   false);
    run_gemm(x,   wv_a, tmp, M, 128,    D,   false);
    run_gemm(tmp, wv_b, v,   M, KVH*HD, 128, true);

    // RoPE on q and k
    {
        int tq = M * H * 64;
        rope_kernel<<<(tq + 255)/256, 256>>>(q, H, tq);
        int tk = M * KVH * 64;
        rope_kernel<<<(tk + 255)/256, 256>>>(k, KVH, tk);
    }

    // attention
    {
        dim3 grid(S/64, H, B);
        attn_kernel<<<grid, 256, SMEM_ATTN>>>(q, k, v, ao);
    }

    // out = ao @ wo_w^T + (ao @ wo_a^T) @ wo_b^T
    run_gemm(ao,  wo_w, out, M, D,   H*HD, false);
    run_gemm(ao,  wo_a, tmp, M, 128, H*HD, false);
    run_gemm(tmp, wo_b, out, M, D,   128,  true);
}

// round 3
// speedup vs baseline: 1.5715x; 1.5715x over previous
#include <cuda_runtime.h>
#include <cuda_bf16.h>
#include <math.h>
#include <stdint.h>

// Problem constants
static constexpr int B = 2, S = 2048, D = 2048;
static constexpr int H = 16, KVH = 4, HD = 128;
static constexpr int MROWS = B * S;            // 4096
static constexpr int WINDOW = 512, GLOBALK = 64;
static constexpr float SCALE = 0.08838834764831845f;  // 1/sqrt(128)

// ------------- scratch (device globals: allocation-free) -------------
__device__ float g_q [(size_t)MROWS * (H * HD)];
__device__ float g_k [(size_t)MROWS * (KVH * HD)];
__device__ float g_v [(size_t)MROWS * (KVH * HD)];
__device__ float g_tmp[(size_t)MROWS * 128];
__device__ float g_ao[(size_t)MROWS * (H * HD)];

// bf16 hi/lo split buffers
__device__ __nv_bfloat16 g_xh[(size_t)MROWS * D];
__device__ __nv_bfloat16 g_xl[(size_t)MROWS * D];
__device__ __nv_bfloat16 g_wh[12189696];
__device__ __nv_bfloat16 g_wl[12189696];
__device__ __nv_bfloat16 g_th[(size_t)MROWS * 128];
__device__ __nv_bfloat16 g_tl[(size_t)MROWS * 128];
__device__ __nv_bfloat16 g_aoh[(size_t)MROWS * (H * HD)];
__device__ __nv_bfloat16 g_aol[(size_t)MROWS * (H * HD)];

// weight pool offsets (elements)
static constexpr size_t OFF_QW = 0;
static constexpr size_t OFF_QA = OFF_QW + 2048*2048;
static constexpr size_t OFF_QB = OFF_QA + 128*2048;
static constexpr size_t OFF_KW = OFF_QB + 2048*128;
static constexpr size_t OFF_KA = OFF_KW + 512*2048;
static constexpr size_t OFF_KB = OFF_KA + 128*2048;
static constexpr size_t OFF_VW = OFF_KB + 512*128;
static constexpr size_t OFF_VA = OFF_VW + 512*2048;
static constexpr size_t OFF_VB = OFF_VA + 128*2048;
static constexpr size_t OFF_OW = OFF_VB + 512*128;
static constexpr size_t OFF_OA = OFF_OW + 2048*2048;
static constexpr size_t OFF_OB = OFF_OA + 128*2048;

// ============================================================
// helpers
// ============================================================
__device__ __forceinline__ uint32_t smem_u32(const void* p) {
    uint32_t a;
    asm("{ .reg .u64 t; cvta.to.shared.u64 t, %1; cvt.u32.u64 %0, t; }"
        : "=r"(a) : "l"(p));
    return a;
}

__device__ __forceinline__ void ldm_x4(uint32_t* r, uint32_t addr) {
    asm volatile("ldmatrix.sync.aligned.m8n8.x4.shared.b16 {%0,%1,%2,%3}, [%4];"
                 : "=r"(r[0]), "=r"(r[1]), "=r"(r[2]), "=r"(r[3]) : "r"(addr));
}

__device__ __forceinline__ void mma16816(float* c, const uint32_t* a, const uint32_t* b) {
    asm volatile(
        "mma.sync.aligned.m16n8k16.row.col.f32.bf16.bf16.f32 "
        "{%0,%1,%2,%3}, {%4,%5,%6,%7}, {%8,%9}, {%0,%1,%2,%3};"
        : "+f"(c[0]), "+f"(c[1]), "+f"(c[2]), "+f"(c[3])
        : "r"(a[0]), "r"(a[1]), "r"(a[2]), "r"(a[3]), "r"(b[0]), "r"(b[1]));
}

// ============================================================
// fp32 -> bf16 hi/lo split converter
// ============================================================
__global__ void cvt_kernel(const float* __restrict__ x,
                           __nv_bfloat16* __restrict__ hi,
                           __nv_bfloat16* __restrict__ lo, int n4)
{
    int i = blockIdx.x * 256 + threadIdx.x;
    if (i >= n4) return;
    float4 v = ((const float4*)x)[i];
    float vv[4] = {v.x, v.y, v.z, v.w};
    __nv_bfloat16 h[4], l[4];
#pragma unroll
    for (int j = 0; j < 4; j++) {
        h[j] = __float2bfloat16(vv[j]);
        l[j] = __float2bfloat16(vv[j] - __bfloat162float(h[j]));
    }
    *(uint2*)&hi[4*(size_t)i] = *(uint2*)h;
    *(uint2*)&lo[4*(size_t)i] = *(uint2*)l;
}

// ============================================================
// mma.sync GEMM: C[M,N] = A[M,K] @ B[N,K]^T  (3-pass split bf16)
// CTA tile BM x BN x 32, 256 threads, warp tile WM x WN.
// SMEM rows padded to 40 bf16 (80B) -> conflict-free ldmatrix.
// ============================================================
template<int BM, int BN, int WM, int WN, bool ACCUM>
__global__ void __launch_bounds__(256) gemm_mma(
    const __nv_bfloat16* __restrict__ Ahi, const __nv_bfloat16* __restrict__ Alo,
    const __nv_bfloat16* __restrict__ Bhi, const __nv_bfloat16* __restrict__ Blo,
    float* __restrict__ C, int M, int N, int K)
{
    constexpr int MT = WM / 16, NT = WN / 8;
    constexpr int NWN = BN / WN;           // warps along N
    __shared__ __align__(16) __nv_bfloat16 sAh[BM * 40];
    __shared__ __align__(16) __nv_bfloat16 sAl[BM * 40];
    __shared__ __align__(16) __nv_bfloat16 sBh[BN * 40];
    __shared__ __align__(16) __nv_bfloat16 sBl[BN * 40];

    const int tid = threadIdx.x, lane = tid & 31, warp = tid >> 5;
    const int bm = blockIdx.y * BM, bn = blockIdx.x * BN;
    const int wm0 = (warp / NWN) * WM, wn0 = (warp % NWN) * WN;

    const uint32_t uAh = smem_u32(sAh), uAl = smem_u32(sAl);
    const uint32_t uBh = smem_u32(sBh), uBl = smem_u32(sBl);

    // ldmatrix lane address components
    const int rowA = ((lane >> 3) & 1) * 8 + (lane & 7);   // + group row
    const int kselA = (lane >> 4) * 8;
    const int rowB = ((lane >> 4) & 1) * 8 + (lane & 7);
    const int kselB = ((lane >> 3) & 1) * 8;

    float acc[MT][NT][4];
#pragma unroll
    for (int i = 0; i < MT; i++)
#pragma unroll
        for (int j = 0; j < NT; j++)
#pragma unroll
            for (int t = 0; t < 4; t++) acc[i][j][t] = 0.f;

    for (int k0 = 0; k0 < K; k0 += 32) {
        __syncthreads();
        // load A tiles (BM x 32) hi+lo
#pragma unroll
        for (int c = tid; c < BM * 4; c += 256) {
            int r = c >> 2, sg = c & 3;
            size_t ga = (size_t)(bm + r) * K + k0 + sg * 8;
            *(uint4*)&sAh[r * 40 + sg * 8] = *(const uint4*)(Ahi + ga);
            *(uint4*)&sAl[r * 40 + sg * 8] = *(const uint4*)(Alo + ga);
        }
        // load B tiles (BN x 32) hi+lo
#pragma unroll
        for (int c = tid; c < BN * 4; c += 256) {
            int r = c >> 2, sg = c & 3;
            size_t gb = (size_t)(bn + r) * K + k0 + sg * 8;
            *(uint4*)&sBh[r * 40 + sg * 8] = *(const uint4*)(Bhi + gb);
            *(uint4*)&sBl[r * 40 + sg * 8] = *(const uint4*)(Blo + gb);
        }
        __syncthreads();

#pragma unroll
        for (int kk = 0; kk < 2; kk++) {
            uint32_t ah[MT][4], al[MT][4], bh[NT][2], bl[NT][2];
#pragma unroll
            for (int mt = 0; mt < MT; mt++) {
                uint32_t off = (uint32_t)((wm0 + mt*16 + rowA) * 40 + kk*16 + kselA) * 2;
                ldm_x4(ah[mt], uAh + off);
                ldm_x4(al[mt], uAl + off);
            }
#pragma unroll
            for (int nb = 0; nb < NT / 2; nb++) {
                uint32_t off = (uint32_t)((wn0 + nb*16 + rowB) * 40 + kk*16 + kselB) * 2;
                uint32_t r4[4];
                ldm_x4(r4, uBh + off);
                bh[nb*2][0] = r4[0]; bh[nb*2][1] = r4[1];
                bh[nb*2+1][0] = r4[2]; bh[nb*2+1][1] = r4[3];
                ldm_x4(r4, uBl + off);
                bl[nb*2][0] = r4[0]; bl[nb*2][1] = r4[1];
                bl[nb*2+1][0] = r4[2]; bl[nb*2+1][1] = r4[3];
            }
            // hi*hi
#pragma unroll
            for (int mt = 0; mt < MT; mt++)
#pragma unroll
                for (int nt = 0; nt < NT; nt++)
                    mma16816(acc[mt][nt], ah[mt], bh[nt]);
            // hi*lo
#pragma unroll
            for (int mt = 0; mt < MT; mt++)
#pragma unroll
                for (int nt = 0; nt < NT; nt++)
                    mma16816(acc[mt][nt], ah[mt], bl[nt]);
            // lo*hi
#pragma unroll
            for (int mt = 0; mt < MT; mt++)
#pragma unroll
                for (int nt = 0; nt < NT; nt++)
                    mma16816(acc[mt][nt], al[mt], bh[nt]);
        }
    }

    // epilogue
    const int crow = lane >> 2, ccol = (lane & 3) * 2;
#pragma unroll
    for (int mt = 0; mt < MT; mt++) {
#pragma unroll
        for (int nt = 0; nt < NT; nt++) {
            int r0 = bm + wm0 + mt*16 + crow;
            int c0 = bn + wn0 + nt*8 + ccol;
            float* p0 = C + (size_t)r0 * N + c0;
            float* p1 = C + (size_t)(r0 + 8) * N + c0;
            if (ACCUM) {
                float2 o0 = *(float2*)p0, o1 = *(float2*)p1;
                o0.x += acc[mt][nt][0]; o0.y += acc[mt][nt][1];
                o1.x += acc[mt][nt][2]; o1.y += acc[mt][nt][3];
                *(float2*)p0 = o0; *(float2*)p1 = o1;
            } else {
                *(float2*)p0 = make_float2(acc[mt][nt][0], acc[mt][nt][1]);
                *(float2*)p1 = make_float2(acc[mt][nt][2], acc[mt][nt][3]);
            }
        }
    }
}

// ============================================================
// RoPE (interleaved pairs), in place.
// ============================================================
__global__ void rope_kernel(float* __restrict__ t, int heads, int total)
{
    int idx = blockIdx.x * 256 + threadIdx.x;
    if (idx >= total) return;
    int d   = idx & 63;
    int row = idx >> 6;
    int s   = (row / heads) & (S - 1);
    double invf = pow(1.0e6, -(double)d / 64.0);
    float ang = (float)s * (float)invf;
    float sn, cs;
    sincosf(ang, &sn, &cs);
    float* p = t + (size_t)row * 128 + 2 * d;
    float xr = p[0], xi = p[1];
    p[0] = xr * cs - xi * sn;
    p[1] = xr * sn + xi * cs;
}

// ============================================================
// Flash-style masked attention (fp32) — unchanged (passing).
// ============================================================
static constexpr int SMEM_ATTN = (64*128 + 64*132 + 64*128 + 64*64) * 4;

__global__ void __launch_bounds__(256) attn_kernel(
    const float* __restrict__ q, const float* __restrict__ k,
    const float* __restrict__ v, float* __restrict__ ao)
{
    extern __shared__ float shf[];
    float* Qs = shf;
    float* Ks = Qs + 64*128;
    float* Vs = Ks + 64*132;
    float* Ps = Vs + 64*128;

    const int qb = blockIdx.x, h = blockIdx.y, b = blockIdx.z;
    const int i0 = qb * 64;
    const int tid = threadIdx.x, lane = tid & 31, warp = tid >> 5;
    const int kvh = h >> 2;

    for (int idx = tid; idx < 64*32; idx += 256) {
        int r = idx >> 5, c4 = idx & 31;
        float4 t = *(const float4*)&q[((size_t)(b*S + i0 + r)) * (H*HD) + h*HD + c4*4];
        t.x *= SCALE; t.y *= SCALE; t.z *= SCALE; t.w *= SCALE;
        *(float4*)&Qs[r*128 + c4*4] = t;
    }

    float m[8], l[8];
    float4 o[8];
#pragma unroll
    for (int rl = 0; rl < 8; rl++) {
        m[rl] = -1e30f; l[rl] = 0.f;
        o[rl].x = o[rl].y = o[rl].z = o[rl].w = 0.f;
    }

    int startb = qb - 8; if (startb < 0) startb = 0;
    const int extra = (startb > 0) ? 1 : 0;
    const int nblk = (qb - startb + 1) + extra;

    for (int bi = 0; bi < nblk; bi++) {
        const int kb = extra ? (bi == 0 ? 0 : startb + bi - 1) : (startb + bi);
        __syncthreads();
        for (int idx = tid; idx < 64*32; idx += 256) {
            int r = idx >> 5, c4 = idx & 31;
            size_t gb = ((size_t)(b*S + kb*64 + r)) * (KVH*HD) + kvh*HD + c4*4;
            float4 kk4 = *(const float4*)&k[gb];
            float4 vv4 = *(const float4*)&v[gb];
            *(float4*)&Ks[r*132 + c4*4] = kk4;
            *(float4*)&Vs[r*128 + c4*4] = vv4;
        }
        __syncthreads();

#pragma unroll 1
        for (int rl = 0; rl < 8; rl++) {
            const int r = warp*8 + rl;
            const int i = i0 + r;
            float s0 = 0.f, s1 = 0.f;
            const float4* qrow = (const float4*)&Qs[r*128];
            const float4* kr0  = (const float4*)&Ks[lane*132];
            const float4* kr1  = (const float4*)&Ks[(lane+32)*132];
#pragma unroll
            for (int d = 0; d < 32; d++) {
                float4 qq = qrow[d];
                float4 ka = kr0[d];
                float4 kb4 = kr1[d];
                s0 += qq.x*ka.x  + qq.y*ka.y  + qq.z*ka.z  + qq.w*ka.w;
                s1 += qq.x*kb4.x + qq.y*kb4.y + qq.z*kb4.z + qq.w*kb4.w;
            }
            const int j0 = kb*64 + lane, j1 = j0 + 32;
            bool a0 = (j0 <= i) && (((i - j0) < WINDOW) || (j0 < GLOBALK));
            bool a1 = (j1 <= i) && (((i - j1) < WINDOW) || (j1 < GLOBALK));
            if (!a0) s0 = -1e30f;
            if (!a1) s1 = -1e30f;

            float smax = fmaxf(s0, s1);
#pragma unroll
            for (int off = 16; off; off >>= 1)
                smax = fmaxf(smax, __shfl_xor_sync(0xffffffffu, smax, off));
            float newm = fmaxf(m[rl], smax);
            float p0 = __expf(s0 - newm);
            float p1 = __expf(s1 - newm);
            float alpha = __expf(m[rl] - newm);
            float psum = p0 + p1;
#pragma unroll
            for (int off = 16; off; off >>= 1)
                psum += __shfl_xor_sync(0xffffffffu, psum, off);
            l[rl] = l[rl] * alpha + psum;
            o[rl].x *= alpha; o[rl].y *= alpha; o[rl].z *= alpha; o[rl].w *= alpha;
            m[rl] = newm;

            Ps[r*64 + lane]      = p0;
            Ps[r*64 + lane + 32] = p1;
            __syncwarp();

            const float* prow = &Ps[r*64];
#pragma unroll 8
            for (int j = 0; j < 64; j++) {
                float p = prow[j];
                float4 vv = *(const float4*)&Vs[j*128 + lane*4];
                o[rl].x += p * vv.x; o[rl].y += p * vv.y;
                o[rl].z += p * vv.z; o[rl].w += p * vv.w;
            }
        }
    }

#pragma unroll
    for (int rl = 0; rl < 8; rl++) {
        const int r = warp*8 + rl;
        const int i = i0 + r;
        float inv = 1.f / l[rl];
        float4 t;
        t.x = o[rl].x * inv; t.y = o[rl].y * inv;
        t.z = o[rl].z * inv; t.w = o[rl].w * inv;
        *(float4*)&ao[((size_t)(b*S + i)) * (H*HD) + h*HD + lane*4] = t;
    }
}

// ============================================================
// Host side
// ============================================================
static inline void cvt(const float* src, __nv_bfloat16* hi, __nv_bfloat16* lo, size_t n)
{
    int n4 = (int)(n / 4);
    cvt_kernel<<<(n4 + 255) / 256, 256>>>(src, hi, lo, n4);
}

static inline void run_gemm_tc(const __nv_bfloat16* Ah, const __nv_bfloat16* Al,
                               const __nv_bfloat16* Bh, const __nv_bfloat16* Bl,
                               float* C, int M, int N, int K, bool accum)
{
    if (N >= 512) {
        dim3 grid(N / 128, M / 128);
        if (accum) gemm_mma<128,128,64,32,true ><<<grid, 256>>>(Ah, Al, Bh, Bl, C, M, N, K);
        else       gemm_mma<128,128,64,32,false><<<grid, 256>>>(Ah, Al, Bh, Bl, C, M, N, K);
    } else {
        dim3 grid(N / 64, M / 64);
        if (accum) gemm_mma<64,64,32,16,true ><<<grid, 256>>>(Ah, Al, Bh, Bl, C, M, N, K);
        else       gemm_mma<64,64,32,16,false><<<grid, 256>>>(Ah, Al, Bh, Bl, C, M, N, K);
    }
}

extern "C" void kernel_launch(void* const* d_in, const int* in_sizes, int n_in,
                              void* d_out, int out_size)
{
    const float* x = (const float*)d_in[0];
    const float* w_in[12] = {
        (const float*)d_in[1],  (const float*)d_in[2],  (const float*)d_in[3],
        (const float*)d_in[4],  (const float*)d_in[5],  (const float*)d_in[6],
        (const float*)d_in[7],  (const float*)d_in[8],  (const float*)d_in[9],
        (const float*)d_in[10], (const float*)d_in[11], (const float*)d_in[12]
    };
    float* out = (float*)d_out;

    float *q, *k, *v, *tmp, *ao;
    __nv_bfloat16 *xh, *xl, *wh, *wl, *th, *tl, *aoh, *aol;
    cudaGetSymbolAddress((void**)&q,   g_q);
    cudaGetSymbolAddress((void**)&k,   g_k);
    cudaGetSymbolAddress((void**)&v,   g_v);
    cudaGetSymbolAddress((void**)&tmp, g_tmp);
    cudaGetSymbolAddress((void**)&ao,  g_ao);
    cudaGetSymbolAddress((void**)&xh,  g_xh);
    cudaGetSymbolAddress((void**)&xl,  g_xl);
    cudaGetSymbolAddress((void**)&wh,  g_wh);
    cudaGetSymbolAddress((void**)&wl,  g_wl);
    cudaGetSymbolAddress((void**)&th,  g_th);
    cudaGetSymbolAddress((void**)&tl,  g_tl);
    cudaGetSymbolAddress((void**)&aoh, g_aoh);
    cudaGetSymbolAddress((void**)&aol, g_aol);

    cudaFuncSetAttribute(attn_kernel,
        cudaFuncAttributeMaxDynamicSharedMemorySize, SMEM_ATTN);

    const int M = MROWS;

    // ---- convert inputs to bf16 hi/lo ----
    cvt(x, xh, xl, (size_t)M * D);
    const size_t woff[12] = {OFF_QW, OFF_QA, OFF_QB, OFF_KW, OFF_KA, OFF_KB,
                             OFF_VW, OFF_VA, OFF_VB, OFF_OW, OFF_OA, OFF_OB};
    const size_t wsz[12]  = {2048*2048, 128*2048, 2048*128,
                             512*2048, 128*2048, 512*128,
                             512*2048, 128*2048, 512*128,
                             2048*2048, 128*2048, 2048*128};
    for (int i = 0; i < 12; i++)
        cvt(w_in[i], wh + woff[i], wl + woff[i], wsz[i]);

    // ---- Q = x@wq_w^T + (x@wq_a^T)@wq_b^T ----
    run_gemm_tc(xh, xl, wh+OFF_QW, wl+OFF_QW, q,   M, H*HD, D,   false);
    run_gemm_tc(xh, xl, wh+OFF_QA, wl+OFF_QA, tmp, M, 128,  D,   false);
    cvt(tmp, th, tl, (size_t)M * 128);
    run_gemm_tc(th, tl, wh+OFF_QB, wl+OFF_QB, q,   M, H*HD, 128, true);
    // ---- K ----
    run_gemm_tc(xh, xl, wh+OFF_KW, wl+OFF_KW, k,   M, KVH*HD, D,   false);
    run_gemm_tc(xh, xl, wh+OFF_KA, wl+OFF_KA, tmp, M, 128,    D,   false);
    cvt(tmp, th, tl, (size_t)M * 128);
    run_gemm_tc(th, tl, wh+OFF_KB, wl+OFF_KB, k,   M, KVH*HD, 128, true);
    // ---- V ----
    run_gemm_tc(xh, xl, wh+OFF_VW, wl+OFF_VW, v,   M, KVH*HD, D,   false);
    run_gemm_tc(xh, xl, wh+OFF_VA, wl+OFF_VA, tmp, M, 128,    D,   false);
    cvt(tmp, th, tl, (size_t)M * 128);
    run_gemm_tc(th, tl, wh+OFF_VB, wl+OFF_VB, v,   M, KVH*HD, 128, true);

    // ---- RoPE ----
    {
        int tq = M * H * 64;
        rope_kernel<<<(tq + 255)/256, 256>>>(q, H, tq);
        int tk = M * KVH * 64;
        rope_kernel<<<(tk + 255)/256, 256>>>(k, KVH, tk);
    }

    // ---- attention ----
    {
        dim3 grid(S/64, H, B);
        attn_kernel<<<grid, 256, SMEM_ATTN>>>(q, k, v, ao);
    }

    // ---- out = ao@wo_w^T + (ao@wo_a^T)@wo_b^T ----
    cvt(ao, aoh, aol, (size_t)M * (H*HD));
    run_gemm_tc(aoh, aol, wh+OFF_OW, wl+OFF_OW, out, M, D,   H*HD, false);
    run_gemm_tc(aoh, aol, wh+OFF_OA, wl+OFF_OA, tmp, M, 128, H*HD, false);
    cvt(tmp, th, tl, (size_t)M * 128);
    run_gemm_tc(th, tl, wh+OFF_OB, wl+OFF_OB, out, M, D,   128,  true);
}

// round 5
// speedup vs baseline: 2.5504x; 1.6229x over previous
#include <cuda_runtime.h>
#include <cuda_bf16.h>
#include <math.h>
#include <stdint.h>

// Problem constants
static constexpr int B = 2, S = 2048, D = 2048;
static constexpr int H = 16, KVH = 4, HD = 128;
static constexpr int MROWS = B * S;            // 4096
static constexpr int WINDOW = 512, GLOBALK = 64;
static constexpr float SCALE = 0.08838834764831845f;  // 1/sqrt(128)

// ------------- scratch (device globals: allocation-free) -------------
__device__ float g_q [(size_t)MROWS * (H * HD)];
__device__ float g_k [(size_t)MROWS * (KVH * HD)];
__device__ float g_v [(size_t)MROWS * (KVH * HD)];
__device__ float g_tmp[(size_t)MROWS * 128];
__device__ float g_ao[(size_t)MROWS * (H * HD)];

// bf16 hi/lo split buffers
__device__ __nv_bfloat16 g_xh[(size_t)MROWS * D];
__device__ __nv_bfloat16 g_xl[(size_t)MROWS * D];
__device__ __nv_bfloat16 g_wh[12189696];
__device__ __nv_bfloat16 g_wl[12189696];
__device__ __nv_bfloat16 g_th[(size_t)MROWS * 128];
__device__ __nv_bfloat16 g_tl[(size_t)MROWS * 128];
__device__ __nv_bfloat16 g_aoh[(size_t)MROWS * (H * HD)];
__device__ __nv_bfloat16 g_aol[(size_t)MROWS * (H * HD)];
// attention operand splits
__device__ __nv_bfloat16 g_qh[(size_t)MROWS * (H * HD)];
__device__ __nv_bfloat16 g_ql[(size_t)MROWS * (H * HD)];
__device__ __nv_bfloat16 g_kh[(size_t)MROWS * (KVH * HD)];
__device__ __nv_bfloat16 g_kl[(size_t)MROWS * (KVH * HD)];
__device__ __nv_bfloat16 g_vh[(size_t)MROWS * (KVH * HD)];
__device__ __nv_bfloat16 g_vl[(size_t)MROWS * (KVH * HD)];

// weight pool offsets (elements)
static constexpr size_t OFF_QW = 0;
static constexpr size_t OFF_QA = OFF_QW + 2048*2048;
static constexpr size_t OFF_QB = OFF_QA + 128*2048;
static constexpr size_t OFF_KW = OFF_QB + 2048*128;
static constexpr size_t OFF_KA = OFF_KW + 512*2048;
static constexpr size_t OFF_KB = OFF_KA + 128*2048;
static constexpr size_t OFF_VW = OFF_KB + 512*128;
static constexpr size_t OFF_VA = OFF_VW + 512*2048;
static constexpr size_t OFF_VB = OFF_VA + 128*2048;
static constexpr size_t OFF_OW = OFF_VB + 512*128;
static constexpr size_t OFF_OA = OFF_OW + 2048*2048;
static constexpr size_t OFF_OB = OFF_OA + 128*2048;

// ============================================================
// helpers
// ============================================================
__device__ __forceinline__ uint32_t smem_u32(const void* p) {
    uint32_t a;
    asm("{ .reg .u64 t; cvta.to.shared.u64 t, %1; cvt.u32.u64 %0, t; }"
        : "=r"(a) : "l"(p));
    return a;
}

__device__ __forceinline__ void ldm_x4(uint32_t* r, uint32_t addr) {
    asm volatile("ldmatrix.sync.aligned.m8n8.x4.shared.b16 {%0,%1,%2,%3}, [%4];"
                 : "=r"(r[0]), "=r"(r[1]), "=r"(r[2]), "=r"(r[3]) : "r"(addr));
}
__device__ __forceinline__ void ldm_x4_t(uint32_t* r, uint32_t addr) {
    asm volatile("ldmatrix.sync.aligned.m8n8.x4.trans.shared.b16 {%0,%1,%2,%3}, [%4];"
                 : "=r"(r[0]), "=r"(r[1]), "=r"(r[2]), "=r"(r[3]) : "r"(addr));
}

__device__ __forceinline__ void mma16816(float* c, const uint32_t* a, const uint32_t* b) {
    asm volatile(
        "mma.sync.aligned.m16n8k16.row.col.f32.bf16.bf16.f32 "
        "{%0,%1,%2,%3}, {%4,%5,%6,%7}, {%8,%9}, {%0,%1,%2,%3};"
        : "+f"(c[0]), "+f"(c[1]), "+f"(c[2]), "+f"(c[3])
        : "r"(a[0]), "r"(a[1]), "r"(a[2]), "r"(a[3]), "r"(b[0]), "r"(b[1]));
}

#define CP16(saddr, gptr) \
    asm volatile("cp.async.cg.shared.global [%0], [%1], 16;" :: "r"(saddr), "l"(gptr))
#define CP_COMMIT() asm volatile("cp.async.commit_group;" ::: "memory")
#define CP_WAIT0()  asm volatile("cp.async.wait_group 0;" ::: "memory")
#define CP_WAIT1()  asm volatile("cp.async.wait_group 1;" ::: "memory")

__device__ __forceinline__ void split2(float x, float y, uint32_t& h, uint32_t& l) {
    __nv_bfloat16 hx = __float2bfloat16(x), hy = __float2bfloat16(y);
    __nv_bfloat16 lx = __float2bfloat16(x - __bfloat162float(hx));
    __nv_bfloat16 ly = __float2bfloat16(y - __bfloat162float(hy));
    uint16_t uhx = *(uint16_t*)&hx, uhy = *(uint16_t*)&hy;
    uint16_t ulx = *(uint16_t*)&lx, uly = *(uint16_t*)&ly;
    h = (uint32_t)uhx | ((uint32_t)uhy << 16);
    l = (uint32_t)ulx | ((uint32_t)uly << 16);
}

// ============================================================
// fp32 -> bf16 hi/lo split converter
// ============================================================
__global__ void cvt_kernel(const float* __restrict__ x,
                           __nv_bfloat16* __restrict__ hi,
                           __nv_bfloat16* __restrict__ lo, int n4)
{
    int i = blockIdx.x * 256 + threadIdx.x;
    if (i >= n4) return;
    float4 v = ((const float4*)x)[i];
    float vv[4] = {v.x, v.y, v.z, v.w};
    __nv_bfloat16 h[4], l[4];
#pragma unroll
    for (int j = 0; j < 4; j++) {
        h[j] = __float2bfloat16(vv[j]);
        l[j] = __float2bfloat16(vv[j] - __bfloat162float(h[j]));
    }
    *(uint2*)&hi[4*(size_t)i] = *(uint2*)h;
    *(uint2*)&lo[4*(size_t)i] = *(uint2*)l;
}

// ============================================================
// fused RoPE (+optional scale) + bf16 hi/lo split
// ============================================================
__global__ void rope_split_kernel(const float* __restrict__ t,
                                  __nv_bfloat16* __restrict__ hi,
                                  __nv_bfloat16* __restrict__ lo,
                                  int heads, float scale, int total)
{
    int idx = blockIdx.x * 256 + threadIdx.x;
    if (idx >= total) return;
    int d   = idx & 63;
    int r   = idx >> 6;
    int s   = (r / heads) & (S - 1);
    double invf = pow(1.0e6, -(double)d / 64.0);
    float ang = (float)s * (float)invf;
    float sn, cs;
    sincosf(ang, &sn, &cs);
    const float* p = t + (size_t)r * 128 + 2 * d;
    float xr = p[0], xi = p[1];
    float o0 = (xr * cs - xi * sn) * scale;
    float o1 = (xr * sn + xi * cs) * scale;
    uint32_t hh, ll;
    split2(o0, o1, hh, ll);
    *(uint32_t*)&hi[(size_t)r * 128 + 2 * d] = hh;
    *(uint32_t*)&lo[(size_t)r * 128 + 2 * d] = ll;
}

// ============================================================
// mma.sync GEMM: C[M,N] = A[M,K] @ B[N,K]^T  (3-pass split bf16)
// cp.async double-buffered, K-chunk 32.
// ============================================================
template<int BM, int BN, int WM, int WN, bool ACCUM>
__global__ void __launch_bounds__(256) gemm_mma(
    const __nv_bfloat16* __restrict__ Ahi, const __nv_bfloat16* __restrict__ Alo,
    const __nv_bfloat16* __restrict__ Bhi, const __nv_bfloat16* __restrict__ Blo,
    float* __restrict__ C, int M, int N, int K)
{
    constexpr int MT = WM / 16, NT = WN / 8;
    constexpr int NWN = BN / WN;
    constexpr int ASZ = BM * 40, BSZ = BN * 40;
    constexpr int STG = 2 * ASZ + 2 * BSZ;
    extern __shared__ char dynsm[];
    __nv_bfloat16* smem = (__nv_bfloat16*)dynsm;

    const int tid = threadIdx.x, lane = tid & 31, warp = tid >> 5;
    const int bm = blockIdx.y * BM, bn = blockIdx.x * BN;
    const int wm0 = (warp / NWN) * WM, wn0 = (warp % NWN) * WN;
    const uint32_t su = smem_u32(smem);

    const int rowA = ((lane >> 3) & 1) * 8 + (lane & 7);
    const int kselA = (lane >> 4) * 8;
    const int rowB = ((lane >> 4) & 1) * 8 + (lane & 7);
    const int kselB = ((lane >> 3) & 1) * 8;

    float acc[MT][NT][4];
#pragma unroll
    for (int i = 0; i < MT; i++)
#pragma unroll
        for (int j = 0; j < NT; j++)
#pragma unroll
            for (int t = 0; t < 4; t++) acc[i][j][t] = 0.f;

    auto load_stage = [&](int st, int k0) {
        uint32_t base = su + (uint32_t)st * STG * 2;
#pragma unroll
        for (int c = tid; c < BM * 4; c += 256) {
            int r = c >> 2, sg = c & 3;
            uint32_t so = (uint32_t)(r * 80 + sg * 16);
            size_t ga = (size_t)(bm + r) * K + k0 + sg * 8;
            CP16(base + so, Ahi + ga);
            CP16(base + ASZ * 2 + so, Alo + ga);
        }
#pragma unroll
        for (int c = tid; c < BN * 4; c += 256) {
            int r = c >> 2, sg = c & 3;
            uint32_t so = (uint32_t)(r * 80 + sg * 16);
            size_t gb = (size_t)(bn + r) * K + k0 + sg * 8;
            CP16(base + 2 * ASZ * 2 + so, Bhi + gb);
            CP16(base + (2 * ASZ + BSZ) * 2 + so, Blo + gb);
        }
    };

    const int nk = K / 32;
    load_stage(0, 0);
    CP_COMMIT();

    for (int kt = 0; kt < nk; kt++) {
        const int buf = kt & 1;
        if (kt + 1 < nk) {
            load_stage((kt + 1) & 1, (kt + 1) * 32);
            CP_COMMIT();
            CP_WAIT1();
        } else {
            CP_WAIT0();
        }
        __syncthreads();

        const uint32_t uAh = su + (uint32_t)buf * STG * 2;
        const uint32_t uAl = uAh + ASZ * 2;
        const uint32_t uBh = uAh + 2 * ASZ * 2;
        const uint32_t uBl = uAh + (2 * ASZ + BSZ) * 2;

#pragma unroll
        for (int kk = 0; kk < 2; kk++) {
            uint32_t ah[MT][4], al[MT][4], bh[NT][2], bl[NT][2];
#pragma unroll
            for (int mt = 0; mt < MT; mt++) {
                uint32_t off = (uint32_t)((wm0 + mt*16 + rowA) * 40 + kk*16 + kselA) * 2;
                ldm_x4(ah[mt], uAh + off);
                ldm_x4(al[mt], uAl + off);
            }
#pragma unroll
            for (int nb = 0; nb < NT / 2; nb++) {
                uint32_t off = (uint32_t)((wn0 + nb*16 + rowB) * 40 + kk*16 + kselB) * 2;
                uint32_t r4[4];
                ldm_x4(r4, uBh + off);
                bh[nb*2][0] = r4[0]; bh[nb*2][1] = r4[1];
                bh[nb*2+1][0] = r4[2]; bh[nb*2+1][1] = r4[3];
                ldm_x4(r4, uBl + off);
                bl[nb*2][0] = r4[0]; bl[nb*2][1] = r4[1];
                bl[nb*2+1][0] = r4[2]; bl[nb*2+1][1] = r4[3];
            }
#pragma unroll
            for (int mt = 0; mt < MT; mt++)
#pragma unroll
                for (int nt = 0; nt < NT; nt++)
                    mma16816(acc[mt][nt], ah[mt], bh[nt]);
#pragma unroll
            for (int mt = 0; mt < MT; mt++)
#pragma unroll
                for (int nt = 0; nt < NT; nt++)
                    mma16816(acc[mt][nt], ah[mt], bl[nt]);
#pragma unroll
            for (int mt = 0; mt < MT; mt++)
#pragma unroll
                for (int nt = 0; nt < NT; nt++)
                    mma16816(acc[mt][nt], al[mt], bh[nt]);
        }
        __syncthreads();
    }

    const int crow = lane >> 2, ccol = (lane & 3) * 2;
#pragma unroll
    for (int mt = 0; mt < MT; mt++) {
#pragma unroll
        for (int nt = 0; nt < NT; nt++) {
            int r0 = bm + wm0 + mt*16 + crow;
            int c0 = bn + wn0 + nt*8 + ccol;
            float* p0 = C + (size_t)r0 * N + c0;
            float* p1 = C + (size_t)(r0 + 8) * N + c0;
            if (ACCUM) {
                float2 o0 = *(float2*)p0, o1 = *(float2*)p1;
                o0.x += acc[mt][nt][0]; o0.y += acc[mt][nt][1];
                o1.x += acc[mt][nt][2]; o1.y += acc[mt][nt][3];
                *(float2*)p0 = o0; *(float2*)p1 = o1;
            } else {
                *(float2*)p0 = make_float2(acc[mt][nt][0], acc[mt][nt][1]);
                *(float2*)p1 = make_float2(acc[mt][nt][2], acc[mt][nt][3]);
            }
        }
    }
}

// ============================================================
// Tensor-core flash attention.
// CTA: 128 q rows x 1 head x 1 batch. 8 warps x 16 rows, 64-key blocks.
// ============================================================
static constexpr int QS_H = 0;                 // 128*136 elems
static constexpr int QS_L = 17408;
static constexpr int KS_H = 34816;             // 64*136
static constexpr int KS_L = 43520;
static constexpr int VS_H = 52224;
static constexpr int VS_L = 60928;
static constexpr int ATTN_SMEM_BYTES = 69632 * 2;   // 139264

__global__ void __launch_bounds__(256) attn_mma_kernel(
    const __nv_bfloat16* __restrict__ qh, const __nv_bfloat16* __restrict__ ql,
    const __nv_bfloat16* __restrict__ kh, const __nv_bfloat16* __restrict__ kl,
    const __nv_bfloat16* __restrict__ vh, const __nv_bfloat16* __restrict__ vl,
    float* __restrict__ ao)
{
    extern __shared__ char dynsm[];
    __nv_bfloat16* sm = (__nv_bfloat16*)dynsm;
    const int qb = blockIdx.x, h = blockIdx.y, b = blockIdx.z;
    const int i0 = qb * 128;
    const int tid = threadIdx.x, lane = tid & 31, warp = tid >> 5;
    const int kvh = h >> 2;
    const uint32_t su = smem_u32(sm);

    // load Q tile (128 x 128) hi/lo
#pragma unroll
    for (int c = tid; c < 128 * 16; c += 256) {
        int r = c >> 4, sg = c & 15;
        size_t g = ((size_t)(b*S + i0 + r)) * (H*HD) + h*HD + sg*8;
        *(uint4*)&sm[QS_H + r*136 + sg*8] = *(const uint4*)(qh + g);
        *(uint4*)&sm[QS_L + r*136 + sg*8] = *(const uint4*)(ql + g);
    }

    float O[16][4];
#pragma unroll
    for (int i = 0; i < 16; i++)
#pragma unroll
        for (int t = 0; t < 4; t++) O[i][t] = 0.f;
    float m0 = -1e30f, m1 = -1e30f, l0 = 0.f, l1 = 0.f;

    const int rowA = ((lane >> 3) & 1) * 8 + (lane & 7);
    const int kselA = (lane >> 4) * 8;
    const int rowB = ((lane >> 4) & 1) * 8 + (lane & 7);
    const int kselB = ((lane >> 3) & 1) * 8;
    const int rowV = ((lane >> 3) & 1) * 8 + (lane & 7);
    const int colV = (lane >> 4) * 8;

    // Window for rows [i0, i0+127] reaches back to key i0-511
    // -> first window key-block is floor((128*qb-511)/64) = 2*qb-8.
    int startb = 2*qb - 8; if (startb < 1) startb = 1;
    const int kb_end = 2*qb + 1;
    const int nblk = 1 + (kb_end - startb + 1);

    const int ir0 = i0 + warp*16 + (lane >> 2);
    const int ir1 = ir0 + 8;

    for (int bi = 0; bi < nblk; bi++) {
        const int kb = (bi == 0) ? 0 : (startb + bi - 1);
        __syncthreads();
#pragma unroll
        for (int c = tid; c < 64 * 16; c += 256) {
            int r = c >> 4, sg = c & 15;
            size_t g = ((size_t)(b*S + kb*64 + r)) * (KVH*HD) + kvh*HD + sg*8;
            *(uint4*)&sm[KS_H + r*136 + sg*8] = *(const uint4*)(kh + g);
            *(uint4*)&sm[KS_L + r*136 + sg*8] = *(const uint4*)(kl + g);
            *(uint4*)&sm[VS_H + r*136 + sg*8] = *(const uint4*)(vh + g);
            *(uint4*)&sm[VS_L + r*136 + sg*8] = *(const uint4*)(vl + g);
        }
        __syncthreads();

        // ---- S = Q K^T  (16 x 64 per warp), 3-pass split ----
        float sc[8][4];
#pragma unroll
        for (int i = 0; i < 8; i++)
#pragma unroll
            for (int t = 0; t < 4; t++) sc[i][t] = 0.f;

#pragma unroll
        for (int kk = 0; kk < 8; kk++) {
            uint32_t ah[4], al[4];
            uint32_t offA = (uint32_t)((warp*16 + rowA)*136 + kk*16 + kselA) * 2;
            ldm_x4(ah, su + QS_H*2 + offA);
            ldm_x4(al, su + QS_L*2 + offA);
#pragma unroll
            for (int g2 = 0; g2 < 4; g2++) {
                uint32_t bh4[4], bl4[4];
                uint32_t offB = (uint32_t)((g2*16 + rowB)*136 + kk*16 + kselB) * 2;
                ldm_x4(bh4, su + KS_H*2 + offB);
                ldm_x4(bl4, su + KS_L*2 + offB);
                mma16816(sc[2*g2],   ah, bh4);
                mma16816(sc[2*g2+1], ah, bh4 + 2);
                mma16816(sc[2*g2],   ah, bl4);
                mma16816(sc[2*g2+1], ah, bl4 + 2);
                mma16816(sc[2*g2],   al, bh4);
                mma16816(sc[2*g2+1], al, bh4 + 2);
            }
        }

        // ---- mask + online softmax ----
        const int jb = kb*64 + (lane & 3) * 2;
        float mx0 = -1e30f, mx1 = -1e30f;
#pragma unroll
        for (int nt = 0; nt < 8; nt++) {
            int j0 = jb + nt*8, j1 = j0 + 1;
            if (!((j0 <= ir0) && (((ir0 - j0) < WINDOW) || (j0 < GLOBALK)))) sc[nt][0] = -1e30f;
            if (!((j1 <= ir0) && (((ir0 - j1) < WINDOW) || (j1 < GLOBALK)))) sc[nt][1] = -1e30f;
            if (!((j0 <= ir1) && (((ir1 - j0) < WINDOW) || (j0 < GLOBALK)))) sc[nt][2] = -1e30f;
            if (!((j1 <= ir1) && (((ir1 - j1) < WINDOW) || (j1 < GLOBALK)))) sc[nt][3] = -1e30f;
            mx0 = fmaxf(mx0, fmaxf(sc[nt][0], sc[nt][1]));
            mx1 = fmaxf(mx1, fmaxf(sc[nt][2], sc[nt][3]));
        }
        mx0 = fmaxf(mx0, __shfl_xor_sync(0xffffffffu, mx0, 1));
        mx0 = fmaxf(mx0, __shfl_xor_sync(0xffffffffu, mx0, 2));
        mx1 = fmaxf(mx1, __shfl_xor_sync(0xffffffffu, mx1, 1));
        mx1 = fmaxf(mx1, __shfl_xor_sync(0xffffffffu, mx1, 2));

        float nm0 = fmaxf(m0, mx0), nm1 = fmaxf(m1, mx1);
        float a0 = __expf(m0 - nm0), a1 = __expf(m1 - nm1);
        float s0 = 0.f, s1 = 0.f;
#pragma unroll
        for (int nt = 0; nt < 8; nt++) {
            sc[nt][0] = __expf(sc[nt][0] - nm0);
            sc[nt][1] = __expf(sc[nt][1] - nm0);
            sc[nt][2] = __expf(sc[nt][2] - nm1);
            sc[nt][3] = __expf(sc[nt][3] - nm1);
            s0 += sc[nt][0] + sc[nt][1];
            s1 += sc[nt][2] + sc[nt][3];
        }
        s0 += __shfl_xor_sync(0xffffffffu, s0, 1);
        s0 += __shfl_xor_sync(0xffffffffu, s0, 2);
        s1 += __shfl_xor_sync(0xffffffffu, s1, 1);
        s1 += __shfl_xor_sync(0xffffffffu, s1, 2);
        l0 = l0 * a0 + s0;  l1 = l1 * a1 + s1;
        m0 = nm0;  m1 = nm1;
#pragma unroll
        for (int dt = 0; dt < 16; dt++) {
            O[dt][0] *= a0; O[dt][1] *= a0;
            O[dt][2] *= a1; O[dt][3] *= a1;
        }

        // ---- O += P V ----
#pragma unroll
        for (int kk = 0; kk < 4; kk++) {
            uint32_t pah[4], pal[4];
            split2(sc[2*kk][0],   sc[2*kk][1],   pah[0], pal[0]);
            split2(sc[2*kk][2],   sc[2*kk][3],   pah[1], pal[1]);
            split2(sc[2*kk+1][0], sc[2*kk+1][1], pah[2], pal[2]);
            split2(sc[2*kk+1][2], sc[2*kk+1][3], pah[3], pal[3]);
#pragma unroll
            for (int dt2 = 0; dt2 < 8; dt2++) {
                uint32_t vbh[4], vbl[4];
                uint32_t offV = (uint32_t)((kk*16 + rowV)*136 + dt2*16 + colV) * 2;
                ldm_x4_t(vbh, su + VS_H*2 + offV);
                ldm_x4_t(vbl, su + VS_L*2 + offV);
                mma16816(O[2*dt2],   pah, vbh);
                mma16816(O[2*dt2+1], pah, vbh + 2);
                mma16816(O[2*dt2],   pal, vbh);
                mma16816(O[2*dt2+1], pal, vbh + 2);
                mma16816(O[2*dt2],   pah, vbl);
                mma16816(O[2*dt2+1], pah, vbl + 2);
            }
        }
    }

    // ---- epilogue ----
    const float inv0 = 1.f / l0, inv1 = 1.f / l1;
    const size_t rbase0 = ((size_t)(b*S + i0 + warp*16 + (lane >> 2))) * (H*HD);
    const size_t rbase1 = rbase0 + 8 * (size_t)(H*HD);
#pragma unroll
    for (int dt = 0; dt < 16; dt++) {
        int cc = h*HD + dt*8 + (lane & 3) * 2;
        *(float2*)&ao[rbase0 + cc] = make_float2(O[dt][0]*inv0, O[dt][1]*inv0);
        *(float2*)&ao[rbase1 + cc] = make_float2(O[dt][2]*inv1, O[dt][3]*inv1);
    }
}

// ============================================================
// Host side
// ============================================================
static inline void cvt(const float* src, __nv_bfloat16* hi, __nv_bfloat16* lo, size_t n)
{
    int n4 = (int)(n / 4);
    cvt_kernel<<<(n4 + 255) / 256, 256>>>(src, hi, lo, n4);
}

static constexpr int SMEM_G128 = 2 * (2*128*40 + 2*128*40) * 2;   // 81920
static constexpr int SMEM_G64  = 2 * (2*64*40 + 2*64*40) * 2;     // 40960

static inline void run_gemm_tc(const __nv_bfloat16* Ah, const __nv_bfloat16* Al,
                               const __nv_bfloat16* Bh, const __nv_bfloat16* Bl,
                               float* C, int M, int N, int K, bool accum)
{
    if (N >= 512) {
        dim3 grid(N / 128, M / 128);
        if (accum) gemm_mma<128,128,64,32,true ><<<grid, 256, SMEM_G128>>>(Ah, Al, Bh, Bl, C, M, N, K);
        else       gemm_mma<128,128,64,32,false><<<grid, 256, SMEM_G128>>>(Ah, Al, Bh, Bl, C, M, N, K);
    } else {
        dim3 grid(N / 64, M / 64);
        if (accum) gemm_mma<64,64,32,16,true ><<<grid, 256, SMEM_G64>>>(Ah, Al, Bh, Bl, C, M, N, K);
        else       gemm_mma<64,64,32,16,false><<<grid, 256, SMEM_G64>>>(Ah, Al, Bh, Bl, C, M, N, K);
    }
}

extern "C" void kernel_launch(void* const* d_in, const int* in_sizes, int n_in,
                              void* d_out, int out_size)
{
    const float* x = (const float*)d_in[0];
    const float* w_in[12] = {
        (const float*)d_in[1],  (const float*)d_in[2],  (const float*)d_in[3],
        (const float*)d_in[4],  (const float*)d_in[5],  (const float*)d_in[6],
        (const float*)d_in[7],  (const float*)d_in[8],  (const float*)d_in[9],
        (const float*)d_in[10], (const float*)d_in[11], (const float*)d_in[12]
    };
    float* out = (float*)d_out;

    float *q, *k, *v, *tmp, *ao;
    __nv_bfloat16 *xh, *xl, *wh, *wl, *th, *tl, *aoh, *aol;
    __nv_bfloat16 *qhp, *qlp, *khp, *klp, *vhp, *vlp;
    cudaGetSymbolAddress((void**)&q,   g_q);
    cudaGetSymbolAddress((void**)&k,   g_k);
    cudaGetSymbolAddress((void**)&v,   g_v);
    cudaGetSymbolAddress((void**)&tmp, g_tmp);
    cudaGetSymbolAddress((void**)&ao,  g_ao);
    cudaGetSymbolAddress((void**)&xh,  g_xh);
    cudaGetSymbolAddress((void**)&xl,  g_xl);
    cudaGetSymbolAddress((void**)&wh,  g_wh);
    cudaGetSymbolAddress((void**)&wl,  g_wl);
    cudaGetSymbolAddress((void**)&th,  g_th);
    cudaGetSymbolAddress((void**)&tl,  g_tl);
    cudaGetSymbolAddress((void**)&aoh, g_aoh);
    cudaGetSymbolAddress((void**)&aol, g_aol);
    cudaGetSymbolAddress((void**)&qhp, g_qh);
    cudaGetSymbolAddress((void**)&qlp, g_ql);
    cudaGetSymbolAddress((void**)&khp, g_kh);
    cudaGetSymbolAddress((void**)&klp, g_kl);
    cudaGetSymbolAddress((void**)&vhp, g_vh);
    cudaGetSymbolAddress((void**)&vlp, g_vl);

    cudaFuncSetAttribute(gemm_mma<128,128,64,32,false>,
        cudaFuncAttributeMaxDynamicSharedMemorySize, SMEM_G128);
    cudaFuncSetAttribute(gemm_mma<128,128,64,32,true>,
        cudaFuncAttributeMaxDynamicSharedMemorySize, SMEM_G128);
    cudaFuncSetAttribute(gemm_mma<64,64,32,16,false>,
        cudaFuncAttributeMaxDynamicSharedMemorySize, SMEM_G64);
    cudaFuncSetAttribute(gemm_mma<64,64,32,16,true>,
        cudaFuncAttributeMaxDynamicSharedMemorySize, SMEM_G64);
    cudaFuncSetAttribute(attn_mma_kernel,
        cudaFuncAttributeMaxDynamicSharedMemorySize, ATTN_SMEM_BYTES);

    const int M = MROWS;

    // ---- convert inputs to bf16 hi/lo ----
    cvt(x, xh, xl, (size_t)M * D);
    const size_t woff[12] = {OFF_QW, OFF_QA, OFF_QB, OFF_KW, OFF_KA, OFF_KB,
                             OFF_VW, OFF_VA, OFF_VB, OFF_OW, OFF_OA, OFF_OB};
    const size_t wsz[12]  = {2048*2048, 128*2048, 2048*128,
                             512*2048, 128*2048, 512*128,
                             512*2048, 128*2048, 512*128,
                             2048*2048, 128*2048, 2048*128};
    for (int i = 0; i < 12; i++)
        cvt(w_in[i], wh + woff[i], wl + woff[i], wsz[i]);

    // ---- Q = x@wq_w^T + (x@wq_a^T)@wq_b^T ----
    run_gemm_tc(xh, xl, wh+OFF_QW, wl+OFF_QW, q,   M, H*HD, D,   false);
    run_gemm_tc(xh, xl, wh+OFF_QA, wl+OFF_QA, tmp, M, 128,  D,   false);
    cvt(tmp, th, tl, (size_t)M * 128);
    run_gemm_tc(th, tl, wh+OFF_QB, wl+OFF_QB, q,   M, H*HD, 128, true);
    // ---- K ----
    run_gemm_tc(xh, xl, wh+OFF_KW, wl+OFF_KW, k,   M, KVH*HD, D,   false);
    run_gemm_tc(xh, xl, wh+OFF_KA, wl+OFF_KA, tmp, M, 128,    D,   false);
    cvt(tmp, th, tl, (size_t)M * 128);
    run_gemm_tc(th, tl, wh+OFF_KB, wl+OFF_KB, k,   M, KVH*HD, 128, true);
    // ---- V ----
    run_gemm_tc(xh, xl, wh+OFF_VW, wl+OFF_VW, v,   M, KVH*HD, D,   false);
    run_gemm_tc(xh, xl, wh+OFF_VA, wl+OFF_VA, tmp, M, 128,    D,   false);
    cvt(tmp, th, tl, (size_t)M * 128);
    run_gemm_tc(th, tl, wh+OFF_VB, wl+OFF_VB, v,   M, KVH*HD, 128, true);

    // ---- RoPE + split ----
    {
        int tq = M * H * 64;
        rope_split_kernel<<<(tq + 255)/256, 256>>>(q, qhp, qlp, H, SCALE, tq);
        int tk = M * KVH * 64;
        rope_split_kernel<<<(tk + 255)/256, 256>>>(k, khp, klp, KVH, 1.0f, tk);
        cvt(v, vhp, vlp, (size_t)M * (KVH*HD));
    }

    // ---- attention ----
    {
        dim3 grid(S/128, H, B);
        attn_mma_kernel<<<grid, 256, ATTN_SMEM_BYTES>>>(qhp, qlp, khp, klp, vhp, vlp, ao);
    }

    // ---- out = ao@wo_w^T + (ao@wo_a^T)@wo_b^T ----
    cvt(ao, aoh, aol, (size_t)M * (H*HD));
    run_gemm_tc(aoh, aol, wh+OFF_OW, wl+OFF_OW, out, M, D,   H*HD, false);
    run_gemm_tc(aoh, aol, wh+OFF_OA, wl+OFF_OA, tmp, M, 128, H*HD, false);
    cvt(tmp, th, tl, (size_t)M * 128);
    run_gemm_tc(th, tl, wh+OFF_OB, wl+OFF_OB, out, M, D,   128,  true);
}

// round 6
// speedup vs baseline: 2.5933x; 1.0168x over previous
#include <cuda_runtime.h>
#include <cuda_bf16.h>
#include <math.h>
#include <stdint.h>

// Problem constants
static constexpr int B = 2, S = 2048, D = 2048;
static constexpr int H = 16, KVH = 4, HD = 128;
static constexpr int MROWS = B * S;            // 4096
static constexpr int WINDOW = 512, GLOBALK = 64;
static constexpr float SCALE = 0.08838834764831845f;  // 1/sqrt(128)

// ------------- scratch (device globals) -------------
__device__ float g_q [(size_t)MROWS * (H * HD)];
__device__ float g_k [(size_t)MROWS * (KVH * HD)];
__device__ float g_v [(size_t)MROWS * (KVH * HD)];

__device__ __nv_bfloat16 g_xh[(size_t)MROWS * D];
__device__ __nv_bfloat16 g_xl[(size_t)MROWS * D];
__device__ __nv_bfloat16 g_wh[12189696];
__device__ __nv_bfloat16 g_wl[12189696];
__device__ __nv_bfloat16 g_th[(size_t)MROWS * 384];
__device__ __nv_bfloat16 g_tl[(size_t)MROWS * 384];
__device__ __nv_bfloat16 g_aoh[(size_t)MROWS * (H * HD)];
__device__ __nv_bfloat16 g_aol[(size_t)MROWS * (H * HD)];
__device__ __nv_bfloat16 g_qh[(size_t)MROWS * (H * HD)];
__device__ __nv_bfloat16 g_ql[(size_t)MROWS * (H * HD)];
__device__ __nv_bfloat16 g_kh[(size_t)MROWS * (KVH * HD)];
__device__ __nv_bfloat16 g_kl[(size_t)MROWS * (KVH * HD)];
__device__ __nv_bfloat16 g_vh[(size_t)MROWS * (KVH * HD)];
__device__ __nv_bfloat16 g_vl[(size_t)MROWS * (KVH * HD)];

// weight pool layout (elements):
// [QKVW: qw(2048) kw(512) vw(512) rows x 2048]
// [A: qa(128) ka(128) va(128) rows x 2048]
// [QB 2048x128][KB 512x128][VB 512x128][OW 2048x2048][OA 128x2048][OB 2048x128]
static constexpr size_t OFF_QKVW = 0;
static constexpr size_t OFF_A    = 6291456;
static constexpr size_t OFF_QB   = 7077888;
static constexpr size_t OFF_KB   = 7340032;
static constexpr size_t OFF_VB   = 7405568;
static constexpr size_t OFF_OW   = 7471104;
static constexpr size_t OFF_OA   = 11665408;
static constexpr size_t OFF_OB   = 11927552;

// ============================================================
// helpers
// ============================================================
__device__ __forceinline__ uint32_t smem_u32(const void* p) {
    uint32_t a;
    asm("{ .reg .u64 t; cvta.to.shared.u64 t, %1; cvt.u32.u64 %0, t; }"
        : "=r"(a) : "l"(p));
    return a;
}
__device__ __forceinline__ void ldm_x4(uint32_t* r, uint32_t addr) {
    asm volatile("ldmatrix.sync.aligned.m8n8.x4.shared.b16 {%0,%1,%2,%3}, [%4];"
                 : "=r"(r[0]), "=r"(r[1]), "=r"(r[2]), "=r"(r[3]) : "r"(addr));
}
__device__ __forceinline__ void ldm_x4_t(uint32_t* r, uint32_t addr) {
    asm volatile("ldmatrix.sync.aligned.m8n8.x4.trans.shared.b16 {%0,%1,%2,%3}, [%4];"
                 : "=r"(r[0]), "=r"(r[1]), "=r"(r[2]), "=r"(r[3]) : "r"(addr));
}
__device__ __forceinline__ void mma16816(float* c, const uint32_t* a, const uint32_t* b) {
    asm volatile(
        "mma.sync.aligned.m16n8k16.row.col.f32.bf16.bf16.f32 "
        "{%0,%1,%2,%3}, {%4,%5,%6,%7}, {%8,%9}, {%0,%1,%2,%3};"
        : "+f"(c[0]), "+f"(c[1]), "+f"(c[2]), "+f"(c[3])
        : "r"(a[0]), "r"(a[1]), "r"(a[2]), "r"(a[3]), "r"(b[0]), "r"(b[1]));
}
#define CP16(saddr, gptr) \
    asm volatile("cp.async.cg.shared.global [%0], [%1], 16;" :: "r"(saddr), "l"(gptr))
#define CP_COMMIT() asm volatile("cp.async.commit_group;" ::: "memory")
#define CP_WAIT0()  asm volatile("cp.async.wait_group 0;" ::: "memory")
#define CP_WAIT1()  asm volatile("cp.async.wait_group 1;" ::: "memory")

__device__ __forceinline__ void split2(float x, float y, uint32_t& h, uint32_t& l) {
    __nv_bfloat16 hx = __float2bfloat16(x), hy = __float2bfloat16(y);
    __nv_bfloat16 lx = __float2bfloat16(x - __bfloat162float(hx));
    __nv_bfloat16 ly = __float2bfloat16(y - __bfloat162float(hy));
    uint16_t uhx = *(uint16_t*)&hx, uhy = *(uint16_t*)&hy;
    uint16_t ulx = *(uint16_t*)&lx, uly = *(uint16_t*)&ly;
    h = (uint32_t)uhx | ((uint32_t)uhy << 16);
    l = (uint32_t)ulx | ((uint32_t)uly << 16);
}

// ============================================================
// converters
// ============================================================
__global__ void cvt_kernel(const float* __restrict__ x,
                           __nv_bfloat16* __restrict__ hi,
                           __nv_bfloat16* __restrict__ lo, int n4)
{
    int i = blockIdx.x * 256 + threadIdx.x;
    if (i >= n4) return;
    float4 v = ((const float4*)x)[i];
    float vv[4] = {v.x, v.y, v.z, v.w};
    __nv_bfloat16 h[4], l[4];
#pragma unroll
    for (int j = 0; j < 4; j++) {
        h[j] = __float2bfloat16(vv[j]);
        l[j] = __float2bfloat16(vv[j] - __bfloat162float(h[j]));
    }
    *(uint2*)&hi[4*(size_t)i] = *(uint2*)h;
    *(uint2*)&lo[4*(size_t)i] = *(uint2*)l;
}

// all 12 weight matrices -> pooled hi/lo, one launch
__global__ void cvtw_kernel(
    const float* p0, const float* p1, const float* p2, const float* p3,
    const float* p4, const float* p5, const float* p6, const float* p7,
    const float* p8, const float* p9, const float* p10, const float* p11,
    __nv_bfloat16* __restrict__ hi, __nv_bfloat16* __restrict__ lo)
{
    // d_in order: qw qa qb kw ka kb vw va vb ow oa ob (float4 units)
    const float* srcs[12] = {p0,p1,p2,p3,p4,p5,p6,p7,p8,p9,p10,p11};
    // prefix of sizes (f4)
    const int pre[13] = {0, 1048576, 1114112, 1179648, 1441792, 1507328,
                         1523712, 1785856, 1851392, 1867776, 2916352,
                         2981888, 3047424};
    // dest offsets in pool (f4)
    const int dst[12] = {0, 1572864, 1769472, 1048576, 1638400, 1835008,
                         1310720, 1703936, 1851392, 1867776, 2916352, 2981888};
    int gi = blockIdx.x * 256 + threadIdx.x;
    if (gi >= 3047424) return;
    int s = 0;
#pragma unroll
    for (int t = 1; t < 12; t++) if (gi >= pre[t]) s = t;
    int local = gi - pre[s];
    float4 v = ((const float4*)srcs[s])[local];
    float vv[4] = {v.x, v.y, v.z, v.w};
    __nv_bfloat16 h[4], l[4];
#pragma unroll
    for (int j = 0; j < 4; j++) {
        h[j] = __float2bfloat16(vv[j]);
        l[j] = __float2bfloat16(vv[j] - __bfloat162float(h[j]));
    }
    size_t o = 4 * ((size_t)dst[s] + local);
    *(uint2*)&hi[o] = *(uint2*)h;
    *(uint2*)&lo[o] = *(uint2*)l;
}

// ============================================================
// fused RoPE (+scale) + bf16 hi/lo split
// ============================================================
__global__ void rope_split_kernel(const float* __restrict__ t,
                                  __nv_bfloat16* __restrict__ hi,
                                  __nv_bfloat16* __restrict__ lo,
                                  int heads, float scale, int total)
{
    int idx = blockIdx.x * 256 + threadIdx.x;
    if (idx >= total) return;
    int d   = idx & 63;
    int r   = idx >> 6;
    int s   = (r / heads) & (S - 1);
    double invf = pow(1.0e6, -(double)d / 64.0);
    float ang = (float)s * (float)invf;
    float sn, cs;
    sincosf(ang, &sn, &cs);
    const float* p = t + (size_t)r * 128 + 2 * d;
    float xr = p[0], xi = p[1];
    float o0 = (xr * cs - xi * sn) * scale;
    float o1 = (xr * sn + xi * cs) * scale;
    uint32_t hh, ll;
    split2(o0, o1, hh, ll);
    *(uint32_t*)&hi[(size_t)r * 128 + 2 * d] = hh;
    *(uint32_t*)&lo[(size_t)r * 128 + 2 * d] = ll;
}

// ============================================================
// mma.sync GEMM: C[M,N] = A[M,K] @ B[N,K]^T (3-pass split bf16)
// cp.async double-buffered, K-chunk 32.
// Epilogue flags: ACCUM (read fp32 C), WRITEF (write fp32), SPLITOUT
// (write split bf16), QKVMAP (route columns to q/k/v buffers).
// ============================================================
template<int BM,int BN,int WM,int WN,bool ACCUM,bool WRITEF,bool SPLITOUT,bool QKVMAP>
__global__ void __launch_bounds__((BM/WM)*(BN/WN)*32) gemm_mma(
    const __nv_bfloat16* __restrict__ Ahi, const __nv_bfloat16* __restrict__ Alo, const int lda,
    const __nv_bfloat16* __restrict__ Bhi, const __nv_bfloat16* __restrict__ Blo, const int ldb,
    float* __restrict__ Cq, float* __restrict__ Ck, float* __restrict__ Cv, const int ldcf,
    __nv_bfloat16* __restrict__ Chi, __nv_bfloat16* __restrict__ Clo, const int ldcs,
    const int M, const int N, const int K)
{
    constexpr int NTHR = (BM/WM)*(BN/WN)*32;
    constexpr int MT = WM/16, NT = WN/8;
    constexpr int NWN = BN/WN;
    constexpr int ASZ = BM*40, BSZ = BN*40;
    constexpr int STG = 2*ASZ + 2*BSZ;
    extern __shared__ char dynsm[];
    __nv_bfloat16* smem = (__nv_bfloat16*)dynsm;

    const int tid = threadIdx.x, lane = tid & 31, warp = tid >> 5;
    const int bm = blockIdx.y * BM, bn = blockIdx.x * BN;
    const int wm0 = (warp / NWN) * WM, wn0 = (warp % NWN) * WN;
    const uint32_t su = smem_u32(smem);

    const int rowA = ((lane >> 3) & 1) * 8 + (lane & 7);
    const int kselA = (lane >> 4) * 8;
    const int rowB = ((lane >> 4) & 1) * 8 + (lane & 7);
    const int kselB = ((lane >> 3) & 1) * 8;

    float acc[MT][NT][4];
#pragma unroll
    for (int i = 0; i < MT; i++)
#pragma unroll
        for (int j = 0; j < NT; j++)
#pragma unroll
            for (int t = 0; t < 4; t++) acc[i][j][t] = 0.f;

    auto load_stage = [&](int st, int k0) {
        uint32_t base = su + (uint32_t)st * STG * 2;
#pragma unroll
        for (int c = tid; c < BM * 4; c += NTHR) {
            int r = c >> 2, sg = c & 3;
            uint32_t so = (uint32_t)(r * 80 + sg * 16);
            size_t ga = (size_t)(bm + r) * lda + k0 + sg * 8;
            CP16(base + so, Ahi + ga);
            CP16(base + ASZ * 2 + so, Alo + ga);
        }
#pragma unroll
        for (int c = tid; c < BN * 4; c += NTHR) {
            int r = c >> 2, sg = c & 3;
            uint32_t so = (uint32_t)(r * 80 + sg * 16);
            size_t gb = (size_t)(bn + r) * ldb + k0 + sg * 8;
            CP16(base + 2 * ASZ * 2 + so, Bhi + gb);
            CP16(base + (2 * ASZ + BSZ) * 2 + so, Blo + gb);
        }
    };

    const int nk = K / 32;
    load_stage(0, 0);
    CP_COMMIT();

    for (int kt = 0; kt < nk; kt++) {
        const int buf = kt & 1;
        if (kt + 1 < nk) {
            load_stage((kt + 1) & 1, (kt + 1) * 32);
            CP_COMMIT();
            CP_WAIT1();
        } else {
            CP_WAIT0();
        }
        __syncthreads();

        const uint32_t uAh = su + (uint32_t)buf * STG * 2;
        const uint32_t uAl = uAh + ASZ * 2;
        const uint32_t uBh = uAh + 2 * ASZ * 2;
        const uint32_t uBl = uAh + (2 * ASZ + BSZ) * 2;

#pragma unroll
        for (int kk = 0; kk < 2; kk++) {
            uint32_t ah[MT][4], al[MT][4], bh[NT][2], bl[NT][2];
#pragma unroll
            for (int mt = 0; mt < MT; mt++) {
                uint32_t off = (uint32_t)((wm0 + mt*16 + rowA) * 40 + kk*16 + kselA) * 2;
                ldm_x4(ah[mt], uAh + off);
                ldm_x4(al[mt], uAl + off);
            }
#pragma unroll
            for (int nb = 0; nb < NT / 2; nb++) {
                uint32_t off = (uint32_t)((wn0 + nb*16 + rowB) * 40 + kk*16 + kselB) * 2;
                uint32_t r4[4];
                ldm_x4(r4, uBh + off);
                bh[nb*2][0] = r4[0]; bh[nb*2][1] = r4[1];
                bh[nb*2+1][0] = r4[2]; bh[nb*2+1][1] = r4[3];
                ldm_x4(r4, uBl + off);
                bl[nb*2][0] = r4[0]; bl[nb*2][1] = r4[1];
                bl[nb*2+1][0] = r4[2]; bl[nb*2+1][1] = r4[3];
            }
#pragma unroll
            for (int mt = 0; mt < MT; mt++)
#pragma unroll
                for (int nt = 0; nt < NT; nt++)
                    mma16816(acc[mt][nt], ah[mt], bh[nt]);
#pragma unroll
            for (int mt = 0; mt < MT; mt++)
#pragma unroll
                for (int nt = 0; nt < NT; nt++)
                    mma16816(acc[mt][nt], ah[mt], bl[nt]);
#pragma unroll
            for (int mt = 0; mt < MT; mt++)
#pragma unroll
                for (int nt = 0; nt < NT; nt++)
                    mma16816(acc[mt][nt], al[mt], bh[nt]);
        }
        __syncthreads();
    }

    // ---- epilogue ----
    const int crow = lane >> 2, ccol = (lane & 3) * 2;
    float* Cf;
    int ldc = ldcf, col0;
    if constexpr (QKVMAP) {
        int bnc = blockIdx.x * BN;
        if (bnc < 2048)      { Cf = Cq; ldc = 2048; col0 = bnc; }
        else if (bnc < 2560) { Cf = Ck; ldc = 512;  col0 = bnc - 2048; }
        else                 { Cf = Cv; ldc = 512;  col0 = bnc - 2560; }
    } else { Cf = Cq; col0 = blockIdx.x * BN; }

#pragma unroll
    for (int mt = 0; mt < MT; mt++) {
#pragma unroll
        for (int nt = 0; nt < NT; nt++) {
            int r0 = bm + wm0 + mt*16 + crow;
            int c0 = col0 + wn0 + nt*8 + ccol;
            float v00 = acc[mt][nt][0], v01 = acc[mt][nt][1];
            float v10 = acc[mt][nt][2], v11 = acc[mt][nt][3];
            if constexpr (ACCUM) {
                float2 o0 = *(float2*)&Cf[(size_t)r0 * ldc + c0];
                float2 o1 = *(float2*)&Cf[(size_t)(r0+8) * ldc + c0];
                v00 += o0.x; v01 += o0.y; v10 += o1.x; v11 += o1.y;
            }
            if constexpr (WRITEF) {
                *(float2*)&Cf[(size_t)r0 * ldc + c0]     = make_float2(v00, v01);
                *(float2*)&Cf[(size_t)(r0+8) * ldc + c0] = make_float2(v10, v11);
            }
            if constexpr (SPLITOUT) {
                uint32_t hh, ll;
                split2(v00, v01, hh, ll);
                *(uint32_t*)&Chi[(size_t)r0 * ldcs + c0] = hh;
                *(uint32_t*)&Clo[(size_t)r0 * ldcs + c0] = ll;
                split2(v10, v11, hh, ll);
                *(uint32_t*)&Chi[(size_t)(r0+8) * ldcs + c0] = hh;
                *(uint32_t*)&Clo[(size_t)(r0+8) * ldcs + c0] = ll;
            }
        }
    }
}

// ============================================================
// Tensor-core flash attention, cp.async 2-stage K/V pipeline.
// CTA: 128 q rows x head x batch; 8 warps x 16 rows; 64-key blocks.
// Writes split bf16 output directly.
// ============================================================
static constexpr int AQ_H = 0;          // 128*136
static constexpr int AQ_L = 17408;
static constexpr int ASTG = 34816;      // elems per stage; stage s at ASTG*(1+s)
static constexpr int AKL = 8704, AVH = 17408, AVL = 26112;   // in-stage offsets
static constexpr int ATTN_SMEM_BYTES = ASTG * 3 * 2;  // 208896

__global__ void __launch_bounds__(256) attn_mma_kernel(
    const __nv_bfloat16* __restrict__ qh, const __nv_bfloat16* __restrict__ ql,
    const __nv_bfloat16* __restrict__ kh, const __nv_bfloat16* __restrict__ kl,
    const __nv_bfloat16* __restrict__ vh, const __nv_bfloat16* __restrict__ vl,
    __nv_bfloat16* __restrict__ aoh, __nv_bfloat16* __restrict__ aol)
{
    extern __shared__ char dynsm[];
    __nv_bfloat16* sm = (__nv_bfloat16*)dynsm;
    const int qb = blockIdx.x, h = blockIdx.y, b = blockIdx.z;
    const int i0 = qb * 128;
    const int tid = threadIdx.x, lane = tid & 31, warp = tid >> 5;
    const int kvh = h >> 2;
    const uint32_t su = smem_u32(sm);

    // load Q tile (128 x 128) hi/lo
#pragma unroll
    for (int c = tid; c < 128 * 16; c += 256) {
        int r = c >> 4, sg = c & 15;
        size_t g = ((size_t)(b*S + i0 + r)) * (H*HD) + h*HD + sg*8;
        *(uint4*)&sm[AQ_H + r*136 + sg*8] = *(const uint4*)(qh + g);
        *(uint4*)&sm[AQ_L + r*136 + sg*8] = *(const uint4*)(ql + g);
    }

    float O[16][4];
#pragma unroll
    for (int i = 0; i < 16; i++)
#pragma unroll
        for (int t = 0; t < 4; t++) O[i][t] = 0.f;
    float m0 = -1e30f, m1 = -1e30f, l0 = 0.f, l1 = 0.f;

    const int rowA = ((lane >> 3) & 1) * 8 + (lane & 7);
    const int kselA = (lane >> 4) * 8;
    const int rowB = ((lane >> 4) & 1) * 8 + (lane & 7);
    const int kselB = ((lane >> 3) & 1) * 8;
    const int rowV = ((lane >> 3) & 1) * 8 + (lane & 7);
    const int colV = (lane >> 4) * 8;

    int startb = 2*qb - 8; if (startb < 1) startb = 1;
    const int kb_end = 2*qb + 1;
    const int nblk = 1 + (kb_end - startb + 1);

    const int ir0 = i0 + warp*16 + (lane >> 2);
    const int ir1 = ir0 + 8;

    auto kbof = [&](int i) { return (i == 0) ? 0 : (startb + i - 1); };
    auto load_kv = [&](int st, int kb) {
        uint32_t base = su + (uint32_t)(ASTG * (1 + st)) * 2;
#pragma unroll
        for (int c = tid; c < 64 * 16; c += 256) {
            int r = c >> 4, sg = c & 15;
            size_t g = ((size_t)(b*S + kb*64 + r)) * (KVH*HD) + kvh*HD + sg*8;
            uint32_t so = (uint32_t)(r*136 + sg*8) * 2;
            CP16(base + so, kh + g);
            CP16(base + AKL*2 + so, kl + g);
            CP16(base + AVH*2 + so, vh + g);
            CP16(base + AVL*2 + so, vl + g);
        }
    };

    load_kv(0, kbof(0));
    CP_COMMIT();
    if (nblk > 1) { load_kv(1, kbof(1)); CP_COMMIT(); }

    for (int bi = 0; bi < nblk; bi++) {
        if (bi + 1 < nblk) CP_WAIT1(); else CP_WAIT0();
        __syncthreads();
        const int kb = kbof(bi);
        const uint32_t sb2 = su + (uint32_t)(ASTG * (1 + (bi & 1))) * 2;

        // ---- S = Q K^T (16 x 64 per warp), 3-pass split ----
        float sc[8][4];
#pragma unroll
        for (int i = 0; i < 8; i++)
#pragma unroll
            for (int t = 0; t < 4; t++) sc[i][t] = 0.f;

#pragma unroll
        for (int kk = 0; kk < 8; kk++) {
            uint32_t ah[4], al[4];
            uint32_t offA = (uint32_t)((warp*16 + rowA)*136 + kk*16 + kselA) * 2;
            ldm_x4(ah, su + AQ_H*2 + offA);
            ldm_x4(al, su + AQ_L*2 + offA);
#pragma unroll
            for (int g2 = 0; g2 < 4; g2++) {
                uint32_t bh4[4], bl4[4];
                uint32_t offB = (uint32_t)((g2*16 + rowB)*136 + kk*16 + kselB) * 2;
                ldm_x4(bh4, sb2 + offB);
                ldm_x4(bl4, sb2 + AKL*2 + offB);
                mma16816(sc[2*g2],   ah, bh4);
                mma16816(sc[2*g2+1], ah, bh4 + 2);
                mma16816(sc[2*g2],   ah, bl4);
                mma16816(sc[2*g2+1], ah, bl4 + 2);
                mma16816(sc[2*g2],   al, bh4);
                mma16816(sc[2*g2+1], al, bh4 + 2);
            }
        }

        // ---- mask + online softmax ----
        const int jb = kb*64 + (lane & 3) * 2;
        float mx0 = -1e30f, mx1 = -1e30f;
#pragma unroll
        for (int nt = 0; nt < 8; nt++) {
            int j0 = jb + nt*8, j1 = j0 + 1;
            if (!((j0 <= ir0) && (((ir0 - j0) < WINDOW) || (j0 < GLOBALK)))) sc[nt][0] = -1e30f;
            if (!((j1 <= ir0) && (((ir0 - j1) < WINDOW) || (j1 < GLOBALK)))) sc[nt][1] = -1e30f;
            if (!((j0 <= ir1) && (((ir1 - j0) < WINDOW) || (j0 < GLOBALK)))) sc[nt][2] = -1e30f;
            if (!((j1 <= ir1) && (((ir1 - j1) < WINDOW) || (j1 < GLOBALK)))) sc[nt][3] = -1e30f;
            mx0 = fmaxf(mx0, fmaxf(sc[nt][0], sc[nt][1]));
            mx1 = fmaxf(mx1, fmaxf(sc[nt][2], sc[nt][3]));
        }
        mx0 = fmaxf(mx0, __shfl_xor_sync(0xffffffffu, mx0, 1));
        mx0 = fmaxf(mx0, __shfl_xor_sync(0xffffffffu, mx0, 2));
        mx1 = fmaxf(mx1, __shfl_xor_sync(0xffffffffu, mx1, 1));
        mx1 = fmaxf(mx1, __shfl_xor_sync(0xffffffffu, mx1, 2));

        float nm0 = fmaxf(m0, mx0), nm1 = fmaxf(m1, mx1);
        float a0 = __expf(m0 - nm0), a1 = __expf(m1 - nm1);
        float s0 = 0.f, s1 = 0.f;
#pragma unroll
        for (int nt = 0; nt < 8; nt++) {
            sc[nt][0] = __expf(sc[nt][0] - nm0);
            sc[nt][1] = __expf(sc[nt][1] - nm0);
            sc[nt][2] = __expf(sc[nt][2] - nm1);
            sc[nt][3] = __expf(sc[nt][3] - nm1);
            s0 += sc[nt][0] + sc[nt][1];
            s1 += sc[nt][2] + sc[nt][3];
        }
        s0 += __shfl_xor_sync(0xffffffffu, s0, 1);
        s0 += __shfl_xor_sync(0xffffffffu, s0, 2);
        s1 += __shfl_xor_sync(0xffffffffu, s1, 1);
        s1 += __shfl_xor_sync(0xffffffffu, s1, 2);
        l0 = l0 * a0 + s0;  l1 = l1 * a1 + s1;
        m0 = nm0;  m1 = nm1;
#pragma unroll
        for (int dt = 0; dt < 16; dt++) {
            O[dt][0] *= a0; O[dt][1] *= a0;
            O[dt][2] *= a1; O[dt][3] *= a1;
        }

        // ---- O += P V ----
#pragma unroll
        for (int kk = 0; kk < 4; kk++) {
            uint32_t pah[4], pal[4];
            split2(sc[2*kk][0],   sc[2*kk][1],   pah[0], pal[0]);
            split2(sc[2*kk][2],   sc[2*kk][3],   pah[1], pal[1]);
            split2(sc[2*kk+1][0], sc[2*kk+1][1], pah[2], pal[2]);
            split2(sc[2*kk+1][2], sc[2*kk+1][3], pah[3], pal[3]);
#pragma unroll
            for (int dt2 = 0; dt2 < 8; dt2++) {
                uint32_t vbh[4], vbl[4];
                uint32_t offV = (uint32_t)((kk*16 + rowV)*136 + dt2*16 + colV) * 2;
                ldm_x4_t(vbh, sb2 + AVH*2 + offV);
                ldm_x4_t(vbl, sb2 + AVL*2 + offV);
                mma16816(O[2*dt2],   pah, vbh);
                mma16816(O[2*dt2+1], pah, vbh + 2);
                mma16816(O[2*dt2],   pal, vbh);
                mma16816(O[2*dt2+1], pal, vbh + 2);
                mma16816(O[2*dt2],   pah, vbl);
                mma16816(O[2*dt2+1], pah, vbl + 2);
            }
        }

        __syncthreads();
        if (bi + 2 < nblk) { load_kv(bi & 1, kbof(bi + 2)); CP_COMMIT(); }
    }

    // ---- epilogue: normalize, split to bf16 hi/lo ----
    const float inv0 = 1.f / l0, inv1 = 1.f / l1;
    const size_t rbase0 = ((size_t)(b*S + i0 + warp*16 + (lane >> 2))) * (H*HD);
    const size_t rbase1 = rbase0 + 8 * (size_t)(H*HD);
#pragma unroll
    for (int dt = 0; dt < 16; dt++) {
        int cc = h*HD + dt*8 + (lane & 3) * 2;
        uint32_t hh, ll;
        split2(O[dt][0]*inv0, O[dt][1]*inv0, hh, ll);
        *(uint32_t*)&aoh[rbase0 + cc] = hh;
        *(uint32_t*)&aol[rbase0 + cc] = ll;
        split2(O[dt][2]*inv1, O[dt][3]*inv1, hh, ll);
        *(uint32_t*)&aoh[rbase1 + cc] = hh;
        *(uint32_t*)&aol[rbase1 + cc] = ll;
    }
}

// ============================================================
// Host side
// ============================================================
static constexpr int SMEM_G128 = 2 * (2*128*40 + 2*128*40) * 2;   // 81920
static constexpr int SMEM_G64  = 2 * (2*64*40 + 2*64*40) * 2;     // 40960

extern "C" void kernel_launch(void* const* d_in, const int* in_sizes, int n_in,
                              void* d_out, int out_size)
{
    const float* x = (const float*)d_in[0];
    float* out = (float*)d_out;

    float *q, *k, *v;
    __nv_bfloat16 *xh, *xl, *wh, *wl, *th, *tl, *aoh, *aol;
    __nv_bfloat16 *qhp, *qlp, *khp, *klp, *vhp, *vlp;
    cudaGetSymbolAddress((void**)&q,   g_q);
    cudaGetSymbolAddress((void**)&k,   g_k);
    cudaGetSymbolAddress((void**)&v,   g_v);
    cudaGetSymbolAddress((void**)&xh,  g_xh);
    cudaGetSymbolAddress((void**)&xl,  g_xl);
    cudaGetSymbolAddress((void**)&wh,  g_wh);
    cudaGetSymbolAddress((void**)&wl,  g_wl);
    cudaGetSymbolAddress((void**)&th,  g_th);
    cudaGetSymbolAddress((void**)&tl,  g_tl);
    cudaGetSymbolAddress((void**)&aoh, g_aoh);
    cudaGetSymbolAddress((void**)&aol, g_aol);
    cudaGetSymbolAddress((void**)&qhp, g_qh);
    cudaGetSymbolAddress((void**)&qlp, g_ql);
    cudaGetSymbolAddress((void**)&khp, g_kh);
    cudaGetSymbolAddress((void**)&klp, g_kl);
    cudaGetSymbolAddress((void**)&vhp, g_vh);
    cudaGetSymbolAddress((void**)&vlp, g_vl);

    // GEMM instantiations
    auto GQKV = gemm_mma<128,128,64,64, false,true ,false,true >;
    auto GA   = gemm_mma<128,128,64,64, false,false,true ,false>;
    auto GACC = gemm_mma<128,128,64,64, true ,true ,false,false>;
    auto GW   = gemm_mma<128,128,64,64, false,true ,false,false>;
    auto GVB  = gemm_mma<128,128,64,64, true ,false,true ,false>;
    auto GOA  = gemm_mma<64,64,32,16,   false,false,true ,false>;

    cudaFuncSetAttribute(GQKV, cudaFuncAttributeMaxDynamicSharedMemorySize, SMEM_G128);
    cudaFuncSetAttribute(GA,   cudaFuncAttributeMaxDynamicSharedMemorySize, SMEM_G128);
    cudaFuncSetAttribute(GACC, cudaFuncAttributeMaxDynamicSharedMemorySize, SMEM_G128);
    cudaFuncSetAttribute(GW,   cudaFuncAttributeMaxDynamicSharedMemorySize, SMEM_G128);
    cudaFuncSetAttribute(GVB,  cudaFuncAttributeMaxDynamicSharedMemorySize, SMEM_G128);
    cudaFuncSetAttribute(GOA,  cudaFuncAttributeMaxDynamicSharedMemorySize, SMEM_G64);
    cudaFuncSetAttribute(attn_mma_kernel,
        cudaFuncAttributeMaxDynamicSharedMemorySize, ATTN_SMEM_BYTES);

    const int M = MROWS;

    // ---- converts ----
    cvt_kernel<<<(M*D/4 + 255)/256, 256>>>(x, xh, xl, M*D/4);
    cvtw_kernel<<<(3047424 + 255)/256, 256>>>(
        (const float*)d_in[1], (const float*)d_in[2], (const float*)d_in[3],
        (const float*)d_in[4], (const float*)d_in[5], (const float*)d_in[6],
        (const float*)d_in[7], (const float*)d_in[8], (const float*)d_in[9],
        (const float*)d_in[10], (const float*)d_in[11], (const float*)d_in[12],
        wh, wl);

    // ---- fused QKV weight GEMM: q|k|v = x @ [wq_w;wk_w;wv_w]^T ----
    GQKV<<<dim3(3072/128, 32), 128, SMEM_G128>>>(
        xh, xl, D, wh+OFF_QKVW, wl+OFF_QKVW, D,
        q, k, v, 0, nullptr, nullptr, 0, M, 3072, D);

    // ---- fused LoRA a-proj: th|tl = split(x @ [wq_a;wk_a;wv_a]^T) ----
    GA<<<dim3(384/128, 32), 128, SMEM_G128>>>(
        xh, xl, D, wh+OFF_A, wl+OFF_A, D,
        nullptr, nullptr, nullptr, 0, th, tl, 384, M, 384, D);

    // ---- LoRA b-projections (accumulate) ----
    GACC<<<dim3(2048/128, 32), 128, SMEM_G128>>>(
        th, tl, 384, wh+OFF_QB, wl+OFF_QB, 128,
        q, nullptr, nullptr, 2048, nullptr, nullptr, 0, M, 2048, 128);
    GACC<<<dim3(512/128, 32), 128, SMEM_G128>>>(
        th+128, tl+128, 384, wh+OFF_KB, wl+OFF_KB, 128,
        k, nullptr, nullptr, 512, nullptr, nullptr, 0, M, 512, 128);
    GVB<<<dim3(512/128, 32), 128, SMEM_G128>>>(
        th+256, tl+256, 384, wh+OFF_VB, wl+OFF_VB, 128,
        v, nullptr, nullptr, 512, vhp, vlp, 512, M, 512, 128);

    // ---- RoPE + split ----
    {
        int tq = M * H * 64;
        rope_split_kernel<<<(tq + 255)/256, 256>>>(q, qhp, qlp, H, SCALE, tq);
        int tk = M * KVH * 64;
        rope_split_kernel<<<(tk + 255)/256, 256>>>(k, khp, klp, KVH, 1.0f, tk);
    }

    // ---- attention (writes split output) ----
    {
        dim3 grid(S/128, H, B);
        attn_mma_kernel<<<grid, 256, ATTN_SMEM_BYTES>>>(
            qhp, qlp, khp, klp, vhp, vlp, aoh, aol);
    }

    // ---- output projection ----
    GW<<<dim3(2048/128, 32), 128, SMEM_G128>>>(
        aoh, aol, 2048, wh+OFF_OW, wl+OFF_OW, 2048,
        out, nullptr, nullptr, 2048, nullptr, nullptr, 0, M, 2048, 2048);
    GOA<<<dim3(128/64, 64), 256, SMEM_G64>>>(
        aoh, aol, 2048, wh+OFF_OA, wl+OFF_OA, 2048,
        nullptr, nullptr, nullptr, 0, th, tl, 128, M, 128, 2048);
    GACC<<<dim3(2048/128, 32), 128, SMEM_G128>>>(
        th, tl, 128, wh+OFF_OB, wl+OFF_OB, 128,
        out, nullptr, nullptr, 2048, nullptr, nullptr, 0, M, 2048, 128);
}

// round 7
// speedup vs baseline: 3.0955x; 1.1937x over previous
#include <cuda_runtime.h>
#include <cuda_fp16.h>
#include <math.h>
#include <stdint.h>

// Problem constants
static constexpr int B = 2, S = 2048, D = 2048;
static constexpr int H = 16, KVH = 4, HD = 128;
static constexpr int MROWS = B * S;            // 4096
static constexpr int WINDOW = 512, GLOBALK = 64;
static constexpr float SCALE = 0.08838834764831845f;  // 1/sqrt(128)

// ------------- scratch (device globals) -------------
__device__ float g_q [(size_t)MROWS * (H * HD)];
__device__ float g_k [(size_t)MROWS * (KVH * HD)];
__device__ float g_v [(size_t)MROWS * (KVH * HD)];

__device__ __half g_xh[(size_t)MROWS * D];
__device__ __half g_wh[12189696];
__device__ __half g_wl[12189696];
__device__ __half g_th[(size_t)MROWS * 384];
__device__ __half g_aoh[(size_t)MROWS * (H * HD)];
__device__ __half g_qh[(size_t)MROWS * (H * HD)];
__device__ __half g_kh[(size_t)MROWS * (KVH * HD)];
__device__ __half g_kl[(size_t)MROWS * (KVH * HD)];
__device__ __half g_vh[(size_t)MROWS * (KVH * HD)];
__device__ __half g_vl[(size_t)MROWS * (KVH * HD)];

// weight pool layout (elements)
static constexpr size_t OFF_QKVW = 0;
static constexpr size_t OFF_A    = 6291456;
static constexpr size_t OFF_QB   = 7077888;
static constexpr size_t OFF_KB   = 7340032;
static constexpr size_t OFF_VB   = 7405568;
static constexpr size_t OFF_OW   = 7471104;
static constexpr size_t OFF_OA   = 11665408;
static constexpr size_t OFF_OB   = 11927552;

// ============================================================
// helpers
// ============================================================
__device__ __forceinline__ uint32_t smem_u32(const void* p) {
    uint32_t a;
    asm("{ .reg .u64 t; cvta.to.shared.u64 t, %1; cvt.u32.u64 %0, t; }"
        : "=r"(a) : "l"(p));
    return a;
}
__device__ __forceinline__ void ldm_x4(uint32_t* r, uint32_t addr) {
    asm volatile("ldmatrix.sync.aligned.m8n8.x4.shared.b16 {%0,%1,%2,%3}, [%4];"
                 : "=r"(r[0]), "=r"(r[1]), "=r"(r[2]), "=r"(r[3]) : "r"(addr));
}
__device__ __forceinline__ void ldm_x4_t(uint32_t* r, uint32_t addr) {
    asm volatile("ldmatrix.sync.aligned.m8n8.x4.trans.shared.b16 {%0,%1,%2,%3}, [%4];"
                 : "=r"(r[0]), "=r"(r[1]), "=r"(r[2]), "=r"(r[3]) : "r"(addr));
}
__device__ __forceinline__ void mma16816(float* c, const uint32_t* a, const uint32_t* b) {
    asm volatile(
        "mma.sync.aligned.m16n8k16.row.col.f32.f16.f16.f32 "
        "{%0,%1,%2,%3}, {%4,%5,%6,%7}, {%8,%9}, {%0,%1,%2,%3};"
        : "+f"(c[0]), "+f"(c[1]), "+f"(c[2]), "+f"(c[3])
        : "r"(a[0]), "r"(a[1]), "r"(a[2]), "r"(a[3]), "r"(b[0]), "r"(b[1]));
}
#define CP16(saddr, gptr) \
    asm volatile("cp.async.cg.shared.global [%0], [%1], 16;" :: "r"(saddr), "l"(gptr))
#define CP_COMMIT() asm volatile("cp.async.commit_group;" ::: "memory")
#define CP_WAIT0()  asm volatile("cp.async.wait_group 0;" ::: "memory")
#define CP_WAIT1()  asm volatile("cp.async.wait_group 1;" ::: "memory")

__device__ __forceinline__ uint32_t packh2(float x, float y) {
    __half2 h = __floats2half2_rn(x, y);
    return *(uint32_t*)&h;
}
// fp16 hi/lo split of a float pair
__device__ __forceinline__ void splith(float x, float y, uint32_t& h, uint32_t& l) {
    __half hx = __float2half_rn(x), hy = __float2half_rn(y);
    __half lx = __float2half_rn(x - __half2float(hx));
    __half ly = __float2half_rn(y - __half2float(hy));
    uint16_t uhx = *(uint16_t*)&hx, uhy = *(uint16_t*)&hy;
    uint16_t ulx = *(uint16_t*)&lx, uly = *(uint16_t*)&ly;
    h = (uint32_t)uhx | ((uint32_t)uhy << 16);
    l = (uint32_t)ulx | ((uint32_t)uly << 16);
}

// ============================================================
// converters
// ============================================================
// x -> fp16 hi only (x is always an A operand)
__global__ void cvtx_kernel(const float* __restrict__ x,
                            __half* __restrict__ hi, int n4)
{
    int i = blockIdx.x * 256 + threadIdx.x;
    if (i >= n4) return;
    float4 v = ((const float4*)x)[i];
    __half h[4] = { __float2half_rn(v.x), __float2half_rn(v.y),
                    __float2half_rn(v.z), __float2half_rn(v.w) };
    *(uint2*)&hi[4*(size_t)i] = *(uint2*)h;
}

// all 12 weight matrices -> pooled fp16 hi/lo, one launch
__global__ void cvtw_kernel(
    const float* p0, const float* p1, const float* p2, const float* p3,
    const float* p4, const float* p5, const float* p6, const float* p7,
    const float* p8, const float* p9, const float* p10, const float* p11,
    __half* __restrict__ hi, __half* __restrict__ lo)
{
    const float* srcs[12] = {p0,p1,p2,p3,p4,p5,p6,p7,p8,p9,p10,p11};
    const int pre[13] = {0, 1048576, 1114112, 1179648, 1441792, 1507328,
                         1523712, 1785856, 1851392, 1867776, 2916352,
                         2981888, 3047424};
    const int dst[12] = {0, 1572864, 1769472, 1048576, 1638400, 1835008,
                         1310720, 1703936, 1851392, 1867776, 2916352, 2981888};
    int gi = blockIdx.x * 256 + threadIdx.x;
    if (gi >= 3047424) return;
    int s = 0;
#pragma unroll
    for (int t = 1; t < 12; t++) if (gi >= pre[t]) s = t;
    int local = gi - pre[s];
    float4 v = ((const float4*)srcs[s])[local];
    uint32_t h01, l01, h23, l23;
    splith(v.x, v.y, h01, l01);
    splith(v.z, v.w, h23, l23);
    size_t o = 4 * ((size_t)dst[s] + local);
    *(uint32_t*)&hi[o]   = h01; *(uint32_t*)&hi[o+2] = h23;
    *(uint32_t*)&lo[o]   = l01; *(uint32_t*)&lo[o+2] = l23;
}

// ============================================================
// fused RoPE (+scale) + fp16 convert (hi, optional lo)
// ============================================================
__global__ void rope_split_kernel(const float* __restrict__ t,
                                  __half* __restrict__ hi,
                                  __half* __restrict__ lo,
                                  int heads, float scale, int total)
{
    int idx = blockIdx.x * 256 + threadIdx.x;
    if (idx >= total) return;
    int d   = idx & 63;
    int r   = idx >> 6;
    int s   = (r / heads) & (S - 1);
    double invf = pow(1.0e6, -(double)d / 64.0);
    float ang = (float)s * (float)invf;
    float sn, cs;
    sincosf(ang, &sn, &cs);
    const float* p = t + (size_t)r * 128 + 2 * d;
    float xr = p[0], xi = p[1];
    float o0 = (xr * cs - xi * sn) * scale;
    float o1 = (xr * sn + xi * cs) * scale;
    uint32_t hh, ll;
    splith(o0, o1, hh, ll);
    *(uint32_t*)&hi[(size_t)r * 128 + 2 * d] = hh;
    if (lo) *(uint32_t*)&lo[(size_t)r * 128 + 2 * d] = ll;
}

// ============================================================
// mma.sync GEMM: C[M,N] = A[M,K] @ B[N,K]^T (2-pass split fp16:
// A-hi x (B-hi + B-lo)). cp.async double-buffered, K-chunk 32.
// ============================================================
template<int BM,int BN,int WM,int WN,bool ACCUM,bool WRITEF,bool SPLITHI,bool SPLITLO,bool QKVMAP>
__global__ void __launch_bounds__((BM/WM)*(BN/WN)*32, 2) gemm_mma(
    const __half* __restrict__ Ahi, const int lda,
    const __half* __restrict__ Bhi, const __half* __restrict__ Blo, const int ldb,
    float* __restrict__ Cq, float* __restrict__ Ck, float* __restrict__ Cv, const int ldcf,
    __half* __restrict__ Chi, __half* __restrict__ Clo, const int ldcs,
    const int M, const int N, const int K)
{
    constexpr int NTHR = (BM/WM)*(BN/WN)*32;
    constexpr int MT = WM/16, NT = WN/8;
    constexpr int NWN = BN/WN;
    constexpr int ASZ = BM*40, BSZ = BN*40;      // halves
    constexpr int STG = ASZ + 2*BSZ;
    extern __shared__ char dynsm[];
    __half* smem = (__half*)dynsm;

    const int tid = threadIdx.x, lane = tid & 31, warp = tid >> 5;
    const int bm = blockIdx.y * BM;
    const int wm0 = (warp / NWN) * WM, wn0 = (warp % NWN) * WN;
    const uint32_t su = smem_u32(smem);

    const int rowA = ((lane >> 3) & 1) * 8 + (lane & 7);
    const int kselA = (lane >> 4) * 8;
    const int rowB = ((lane >> 4) & 1) * 8 + (lane & 7);
    const int kselB = ((lane >> 3) & 1) * 8;

    float acc[MT][NT][4];
#pragma unroll
    for (int i = 0; i < MT; i++)
#pragma unroll
        for (int j = 0; j < NT; j++)
#pragma unroll
            for (int t = 0; t < 4; t++) acc[i][j][t] = 0.f;

    auto load_stage = [&](int st, int k0) {
        uint32_t base = su + (uint32_t)st * STG * 2;
#pragma unroll
        for (int c = tid; c < BM * 4; c += NTHR) {
            int r = c >> 2, sg = c & 3;
            uint32_t so = (uint32_t)(r * 80 + sg * 16);
            size_t ga = (size_t)(bm + r) * lda + k0 + sg * 8;
            CP16(base + so, Ahi + ga);
        }
#pragma unroll
        for (int c = tid; c < BN * 4; c += NTHR) {
            int r = c >> 2, sg = c & 3;
            uint32_t so = (uint32_t)(r * 80 + sg * 16);
            size_t gb = (size_t)((size_t)blockIdx.x * BN + r) * ldb + k0 + sg * 8;
            CP16(base + ASZ * 2 + so, Bhi + gb);
            CP16(base + (ASZ + BSZ) * 2 + so, Blo + gb);
        }
    };

    const int nk = K / 32;
    load_stage(0, 0);
    CP_COMMIT();

    for (int kt = 0; kt < nk; kt++) {
        const int buf = kt & 1;
        if (kt + 1 < nk) {
            load_stage((kt + 1) & 1, (kt + 1) * 32);
            CP_COMMIT();
            CP_WAIT1();
        } else {
            CP_WAIT0();
        }
        __syncthreads();

        const uint32_t uAh = su + (uint32_t)buf * STG * 2;
        const uint32_t uBh = uAh + ASZ * 2;
        const uint32_t uBl = uAh + (ASZ + BSZ) * 2;

#pragma unroll
        for (int kk = 0; kk < 2; kk++) {
            uint32_t ah[MT][4], bh[NT][2], bl[NT][2];
#pragma unroll
            for (int mt = 0; mt < MT; mt++) {
                uint32_t off = (uint32_t)((wm0 + mt*16 + rowA) * 40 + kk*16 + kselA) * 2;
                ldm_x4(ah[mt], uAh + off);
            }
#pragma unroll
            for (int nb = 0; nb < NT / 2; nb++) {
                uint32_t off = (uint32_t)((wn0 + nb*16 + rowB) * 40 + kk*16 + kselB) * 2;
                uint32_t r4[4];
                ldm_x4(r4, uBh + off);
                bh[nb*2][0] = r4[0]; bh[nb*2][1] = r4[1];
                bh[nb*2+1][0] = r4[2]; bh[nb*2+1][1] = r4[3];
                ldm_x4(r4, uBl + off);
                bl[nb*2][0] = r4[0]; bl[nb*2][1] = r4[1];
                bl[nb*2+1][0] = r4[2]; bl[nb*2+1][1] = r4[3];
            }
#pragma unroll
            for (int mt = 0; mt < MT; mt++)
#pragma unroll
                for (int nt = 0; nt < NT; nt++)
                    mma16816(acc[mt][nt], ah[mt], bh[nt]);
#pragma unroll
            for (int mt = 0; mt < MT; mt++)
#pragma unroll
                for (int nt = 0; nt < NT; nt++)
                    mma16816(acc[mt][nt], ah[mt], bl[nt]);
        }
        __syncthreads();
    }

    // ---- epilogue ----
    const int crow = lane >> 2, ccol = (lane & 3) * 2;
    float* Cf;
    int ldc = ldcf, col0;
    if constexpr (QKVMAP) {
        int bnc = blockIdx.x * BN;
        if (bnc < 2048)      { Cf = Cq; ldc = 2048; col0 = bnc; }
        else if (bnc < 2560) { Cf = Ck; ldc = 512;  col0 = bnc - 2048; }
        else                 { Cf = Cv; ldc = 512;  col0 = bnc - 2560; }
    } else { Cf = Cq; col0 = blockIdx.x * BN; }

#pragma unroll
    for (int mt = 0; mt < MT; mt++) {
#pragma unroll
        for (int nt = 0; nt < NT; nt++) {
            int r0 = bm + wm0 + mt*16 + crow;
            int c0 = col0 + wn0 + nt*8 + ccol;
            float v00 = acc[mt][nt][0], v01 = acc[mt][nt][1];
            float v10 = acc[mt][nt][2], v11 = acc[mt][nt][3];
            if constexpr (ACCUM) {
                float2 o0 = *(float2*)&Cf[(size_t)r0 * ldc + c0];
                float2 o1 = *(float2*)&Cf[(size_t)(r0+8) * ldc + c0];
                v00 += o0.x; v01 += o0.y; v10 += o1.x; v11 += o1.y;
            }
            if constexpr (WRITEF) {
                *(float2*)&Cf[(size_t)r0 * ldc + c0]     = make_float2(v00, v01);
                *(float2*)&Cf[(size_t)(r0+8) * ldc + c0] = make_float2(v10, v11);
            }
            if constexpr (SPLITHI) {
                uint32_t hh, ll;
                splith(v00, v01, hh, ll);
                *(uint32_t*)&Chi[(size_t)r0 * ldcs + c0] = hh;
                if constexpr (SPLITLO) *(uint32_t*)&Clo[(size_t)r0 * ldcs + c0] = ll;
                splith(v10, v11, hh, ll);
                *(uint32_t*)&Chi[(size_t)(r0+8) * ldcs + c0] = hh;
                if constexpr (SPLITLO) *(uint32_t*)&Clo[(size_t)(r0+8) * ldcs + c0] = ll;
            }
        }
    }
}

// ============================================================
// Tensor-core flash attention, 2-pass fp16, cp.async K/V pipeline.
// CTA: 128 q rows x head x batch; 8 warps x 16 rows; 64-key blocks.
// ============================================================
static constexpr int AQ_H = 0;          // 128*136 halves
static constexpr int ASTG = 34816;      // halves per stage; stage s at 17408 + s*ASTG
static constexpr int AKL = 8704, AVH = 17408, AVL = 26112;   // in-stage offsets
static constexpr int ATTN_SMEM_BYTES = (17408 + 2 * ASTG) * 2;  // 174080

__global__ void __launch_bounds__(256) attn_mma_kernel(
    const __half* __restrict__ qh,
    const __half* __restrict__ kh, const __half* __restrict__ kl,
    const __half* __restrict__ vh, const __half* __restrict__ vl,
    __half* __restrict__ aoh)
{
    extern __shared__ char dynsm[];
    __half* sm = (__half*)dynsm;
    const int qb = blockIdx.x, h = blockIdx.y, b = blockIdx.z;
    const int i0 = qb * 128;
    const int tid = threadIdx.x, lane = tid & 31, warp = tid >> 5;
    const int kvh = h >> 2;
    const uint32_t su = smem_u32(sm);

    // load Q tile (128 x 128) hi
#pragma unroll
    for (int c = tid; c < 128 * 16; c += 256) {
        int r = c >> 4, sg = c & 15;
        size_t g = ((size_t)(b*S + i0 + r)) * (H*HD) + h*HD + sg*8;
        *(uint4*)&sm[AQ_H + r*136 + sg*8] = *(const uint4*)(qh + g);
    }

    float O[16][4];
#pragma unroll
    for (int i = 0; i < 16; i++)
#pragma unroll
        for (int t = 0; t < 4; t++) O[i][t] = 0.f;
    float m0 = -1e30f, m1 = -1e30f, l0 = 0.f, l1 = 0.f;

    const int rowA = ((lane >> 3) & 1) * 8 + (lane & 7);
    const int kselA = (lane >> 4) * 8;
    const int rowB = ((lane >> 4) & 1) * 8 + (lane & 7);
    const int kselB = ((lane >> 3) & 1) * 8;
    const int rowV = ((lane >> 3) & 1) * 8 + (lane & 7);
    const int colV = (lane >> 4) * 8;

    int startb = 2*qb - 8; if (startb < 1) startb = 1;
    const int kb_end = 2*qb + 1;
    const int nblk = 1 + (kb_end - startb + 1);

    const int ir0 = i0 + warp*16 + (lane >> 2);
    const int ir1 = ir0 + 8;

    auto kbof = [&](int i) { return (i == 0) ? 0 : (startb + i - 1); };
    auto load_kv = [&](int st, int kb) {
        uint32_t base = su + (uint32_t)(17408 + ASTG * st) * 2;
#pragma unroll
        for (int c = tid; c < 64 * 16; c += 256) {
            int r = c >> 4, sg = c & 15;
            size_t g = ((size_t)(b*S + kb*64 + r)) * (KVH*HD) + kvh*HD + sg*8;
            uint32_t so = (uint32_t)(r*136 + sg*8) * 2;
            CP16(base + so, kh + g);
            CP16(base + AKL*2 + so, kl + g);
            CP16(base + AVH*2 + so, vh + g);
            CP16(base + AVL*2 + so, vl + g);
        }
    };

    load_kv(0, kbof(0));
    CP_COMMIT();
    if (nblk > 1) { load_kv(1, kbof(1)); CP_COMMIT(); }

    for (int bi = 0; bi < nblk; bi++) {
        if (bi + 1 < nblk) CP_WAIT1(); else CP_WAIT0();
        __syncthreads();
        const int kb = kbof(bi);
        const uint32_t sb2 = su + (uint32_t)(17408 + ASTG * (bi & 1)) * 2;

        // ---- S = Q K^T (16 x 64 per warp), 2-pass fp16 ----
        float sc[8][4];
#pragma unroll
        for (int i = 0; i < 8; i++)
#pragma unroll
            for (int t = 0; t < 4; t++) sc[i][t] = 0.f;

#pragma unroll
        for (int kk = 0; kk < 8; kk++) {
            uint32_t ah[4];
            uint32_t offA = (uint32_t)((warp*16 + rowA)*136 + kk*16 + kselA) * 2;
            ldm_x4(ah, su + AQ_H*2 + offA);
#pragma unroll
            for (int g2 = 0; g2 < 4; g2++) {
                uint32_t bh4[4], bl4[4];
                uint32_t offB = (uint32_t)((g2*16 + rowB)*136 + kk*16 + kselB) * 2;
                ldm_x4(bh4, sb2 + offB);
                ldm_x4(bl4, sb2 + AKL*2 + offB);
                mma16816(sc[2*g2],   ah, bh4);
                mma16816(sc[2*g2+1], ah, bh4 + 2);
                mma16816(sc[2*g2],   ah, bl4);
                mma16816(sc[2*g2+1], ah, bl4 + 2);
            }
        }

        // ---- mask + online softmax ----
        const int jb = kb*64 + (lane & 3) * 2;
        float mx0 = -1e30f, mx1 = -1e30f;
#pragma unroll
        for (int nt = 0; nt < 8; nt++) {
            int j0 = jb + nt*8, j1 = j0 + 1;
            if (!((j0 <= ir0) && (((ir0 - j0) < WINDOW) || (j0 < GLOBALK)))) sc[nt][0] = -1e30f;
            if (!((j1 <= ir0) && (((ir0 - j1) < WINDOW) || (j1 < GLOBALK)))) sc[nt][1] = -1e30f;
            if (!((j0 <= ir1) && (((ir1 - j0) < WINDOW) || (j0 < GLOBALK)))) sc[nt][2] = -1e30f;
            if (!((j1 <= ir1) && (((ir1 - j1) < WINDOW) || (j1 < GLOBALK)))) sc[nt][3] = -1e30f;
            mx0 = fmaxf(mx0, fmaxf(sc[nt][0], sc[nt][1]));
            mx1 = fmaxf(mx1, fmaxf(sc[nt][2], sc[nt][3]));
        }
        mx0 = fmaxf(mx0, __shfl_xor_sync(0xffffffffu, mx0, 1));
        mx0 = fmaxf(mx0, __shfl_xor_sync(0xffffffffu, mx0, 2));
        mx1 = fmaxf(mx1, __shfl_xor_sync(0xffffffffu, mx1, 1));
        mx1 = fmaxf(mx1, __shfl_xor_sync(0xffffffffu, mx1, 2));

        float nm0 = fmaxf(m0, mx0), nm1 = fmaxf(m1, mx1);
        float a0 = __expf(m0 - nm0), a1 = __expf(m1 - nm1);
        float s0 = 0.f, s1 = 0.f;
#pragma unroll
        for (int nt = 0; nt < 8; nt++) {
            sc[nt][0] = __expf(sc[nt][0] - nm0);
            sc[nt][1] = __expf(sc[nt][1] - nm0);
            sc[nt][2] = __expf(sc[nt][2] - nm1);
            sc[nt][3] = __expf(sc[nt][3] - nm1);
            s0 += sc[nt][0] + sc[nt][1];
            s1 += sc[nt][2] + sc[nt][3];
        }
        s0 += __shfl_xor_sync(0xffffffffu, s0, 1);
        s0 += __shfl_xor_sync(0xffffffffu, s0, 2);
        s1 += __shfl_xor_sync(0xffffffffu, s1, 1);
        s1 += __shfl_xor_sync(0xffffffffu, s1, 2);
        l0 = l0 * a0 + s0;  l1 = l1 * a1 + s1;
        m0 = nm0;  m1 = nm1;
#pragma unroll
        for (int dt = 0; dt < 16; dt++) {
            O[dt][0] *= a0; O[dt][1] *= a0;
            O[dt][2] *= a1; O[dt][3] *= a1;
        }

        // ---- O += P V (P plain fp16; V hi+lo, 2 passes) ----
#pragma unroll
        for (int kk = 0; kk < 4; kk++) {
            uint32_t pah[4];
            pah[0] = packh2(sc[2*kk][0],   sc[2*kk][1]);
            pah[1] = packh2(sc[2*kk][2],   sc[2*kk][3]);
            pah[2] = packh2(sc[2*kk+1][0], sc[2*kk+1][1]);
            pah[3] = packh2(sc[2*kk+1][2], sc[2*kk+1][3]);
#pragma unroll
            for (int dt2 = 0; dt2 < 8; dt2++) {
                uint32_t vbh[4], vbl[4];
                uint32_t offV = (uint32_t)((kk*16 + rowV)*136 + dt2*16 + colV) * 2;
                ldm_x4_t(vbh, sb2 + AVH*2 + offV);
                ldm_x4_t(vbl, sb2 + AVL*2 + offV);
                mma16816(O[2*dt2],   pah, vbh);
                mma16816(O[2*dt2+1], pah, vbh + 2);
                mma16816(O[2*dt2],   pah, vbl);
                mma16816(O[2*dt2+1], pah, vbl + 2);
            }
        }

        __syncthreads();
        if (bi + 2 < nblk) { load_kv(bi & 1, kbof(bi + 2)); CP_COMMIT(); }
    }

    // ---- epilogue: normalize, fp16 hi out ----
    const float inv0 = 1.f / l0, inv1 = 1.f / l1;
    const size_t rbase0 = ((size_t)(b*S + i0 + warp*16 + (lane >> 2))) * (H*HD);
    const size_t rbase1 = rbase0 + 8 * (size_t)(H*HD);
#pragma unroll
    for (int dt = 0; dt < 16; dt++) {
        int cc = h*HD + dt*8 + (lane & 3) * 2;
        *(uint32_t*)&aoh[rbase0 + cc] = packh2(O[dt][0]*inv0, O[dt][1]*inv0);
        *(uint32_t*)&aoh[rbase1 + cc] = packh2(O[dt][2]*inv1, O[dt][3]*inv1);
    }
}

// ============================================================
// Host side
// ============================================================
static constexpr int SMEM_G128 = 2 * (128*40 + 2*128*40) * 2;   // 61440
static constexpr int SMEM_G64  = 2 * (64*40 + 2*64*40) * 2;     // 30720

extern "C" void kernel_launch(void* const* d_in, const int* in_sizes, int n_in,
                              void* d_out, int out_size)
{
    const float* x = (const float*)d_in[0];
    float* out = (float*)d_out;

    float *q, *k, *v;
    __half *xh, *wh, *wl, *th, *aoh, *qhp, *khp, *klp, *vhp, *vlp;
    cudaGetSymbolAddress((void**)&q,   g_q);
    cudaGetSymbolAddress((void**)&k,   g_k);
    cudaGetSymbolAddress((void**)&v,   g_v);
    cudaGetSymbolAddress((void**)&xh,  g_xh);
    cudaGetSymbolAddress((void**)&wh,  g_wh);
    cudaGetSymbolAddress((void**)&wl,  g_wl);
    cudaGetSymbolAddress((void**)&th,  g_th);
    cudaGetSymbolAddress((void**)&aoh, g_aoh);
    cudaGetSymbolAddress((void**)&qhp, g_qh);
    cudaGetSymbolAddress((void**)&khp, g_kh);
    cudaGetSymbolAddress((void**)&klp, g_kl);
    cudaGetSymbolAddress((void**)&vhp, g_vh);
    cudaGetSymbolAddress((void**)&vlp, g_vl);

    // GEMM instantiations:            ACC  WF   SH   SL   QKV
    auto GQKV = gemm_mma<128,128,64,64, false,true ,false,false,true >;
    auto GA   = gemm_mma<128,128,64,64, false,false,true ,false,false>;
    auto GACC = gemm_mma<128,128,64,64, true ,true ,false,false,false>;
    auto GW   = gemm_mma<128,128,64,64, false,true ,false,false,false>;
    auto GVB  = gemm_mma<128,128,64,64, true ,false,true ,true ,false>;
    auto GOA  = gemm_mma<64,64,32,16,   false,false,true ,false,false>;

    cudaFuncSetAttribute(GQKV, cudaFuncAttributeMaxDynamicSharedMemorySize, SMEM_G128);
    cudaFuncSetAttribute(GA,   cudaFuncAttributeMaxDynamicSharedMemorySize, SMEM_G128);
    cudaFuncSetAttribute(GACC, cudaFuncAttributeMaxDynamicSharedMemorySize, SMEM_G128);
    cudaFuncSetAttribute(GW,   cudaFuncAttributeMaxDynamicSharedMemorySize, SMEM_G128);
    cudaFuncSetAttribute(GVB,  cudaFuncAttributeMaxDynamicSharedMemorySize, SMEM_G128);
    cudaFuncSetAttribute(GOA,  cudaFuncAttributeMaxDynamicSharedMemorySize, SMEM_G64);
    cudaFuncSetAttribute(attn_mma_kernel,
        cudaFuncAttributeMaxDynamicSharedMemorySize, ATTN_SMEM_BYTES);

    const int M = MROWS;

    // ---- converts ----
    cvtx_kernel<<<(M*D/4 + 255)/256, 256>>>(x, xh, M*D/4);
    cvtw_kernel<<<(3047424 + 255)/256, 256>>>(
        (const float*)d_in[1], (const float*)d_in[2], (const float*)d_in[3],
        (const float*)d_in[4], (const float*)d_in[5], (const float*)d_in[6],
        (const float*)d_in[7], (const float*)d_in[8], (const float*)d_in[9],
        (const float*)d_in[10], (const float*)d_in[11], (const float*)d_in[12],
        wh, wl);

    // ---- fused QKV weight GEMM: q|k|v = x @ [wq_w;wk_w;wv_w]^T ----
    GQKV<<<dim3(3072/128, 32), 128, SMEM_G128>>>(
        xh, D, wh+OFF_QKVW, wl+OFF_QKVW, D,
        q, k, v, 0, nullptr, nullptr, 0, M, 3072, D);

    // ---- fused LoRA a-proj: th = fp16(x @ [wq_a;wk_a;wv_a]^T) ----
    GA<<<dim3(384/128, 32), 128, SMEM_G128>>>(
        xh, D, wh+OFF_A, wl+OFF_A, D,
        nullptr, nullptr, nullptr, 0, th, nullptr, 384, M, 384, D);

    // ---- LoRA b-projections (accumulate) ----
    GACC<<<dim3(2048/128, 32), 128, SMEM_G128>>>(
        th, 384, wh+OFF_QB, wl+OFF_QB, 128,
        q, nullptr, nullptr, 2048, nullptr, nullptr, 0, M, 2048, 128);
    GACC<<<dim3(512/128, 32), 128, SMEM_G128>>>(
        th+128, 384, wh+OFF_KB, wl+OFF_KB, 128,
        k, nullptr, nullptr, 512, nullptr, nullptr, 0, M, 512, 128);
    GVB<<<dim3(512/128, 32), 128, SMEM_G128>>>(
        th+256, 384, wh+OFF_VB, wl+OFF_VB, 128,
        v, nullptr, nullptr, 512, vhp, vlp, 512, M, 512, 128);

    // ---- RoPE + fp16 convert (q: hi only; k: hi+lo) ----
    {
        int tq = M * H * 64;
        rope_split_kernel<<<(tq + 255)/256, 256>>>(q, qhp, nullptr, H, SCALE, tq);
        int tk = M * KVH * 64;
        rope_split_kernel<<<(tk + 255)/256, 256>>>(k, khp, klp, KVH, 1.0f, tk);
    }

    // ---- attention ----
    {
        dim3 grid(S/128, H, B);
        attn_mma_kernel<<<grid, 256, ATTN_SMEM_BYTES>>>(
            qhp, khp, klp, vhp, vlp, aoh);
    }

    // ---- output projection ----
    GW<<<dim3(2048/128, 32), 128, SMEM_G128>>>(
        aoh, 2048, wh+OFF_OW, wl+OFF_OW, 2048,
        out, nullptr, nullptr, 2048, nullptr, nullptr, 0, M, 2048, 2048);
    GOA<<<dim3(128/64, 64), 256, SMEM_G64>>>(
        aoh, 2048, wh+OFF_OA, wl+OFF_OA, 2048,
        nullptr, nullptr, nullptr, 0, th, nullptr, 128, M, 128, 2048);
    GACC<<<dim3(2048/128, 32), 128, SMEM_G128>>>(
        th, 128, wh+OFF_OB, wl+OFF_OB, 128,
        out, nullptr, nullptr, 2048, nullptr, nullptr, 0, M, 2048, 128);
}

// round 8
// speedup vs baseline: 3.2949x; 1.0644x over previous
#include <cuda_runtime.h>
#include <cuda_fp16.h>
#include <math.h>
#include <stdint.h>

// Problem constants
static constexpr int B = 2, S = 2048, D = 2048;
static constexpr int H = 16, KVH = 4, HD = 128;
static constexpr int MROWS = B * S;            // 4096
static constexpr int WINDOW = 512, GLOBALK = 64;
static constexpr float SCALE = 0.08838834764831845f;  // 1/sqrt(128)

// ------------- scratch (device globals) -------------
__device__ float g_q [(size_t)MROWS * (H * HD)];
__device__ float g_k [(size_t)MROWS * (KVH * HD)];
__device__ float g_v [(size_t)MROWS * (KVH * HD)];

__device__ __half g_xh[(size_t)MROWS * D];
__device__ __half g_wh[12189696];
__device__ __half g_wl[12189696];
__device__ __half g_th[(size_t)MROWS * 384];
__device__ __half g_aoh[(size_t)MROWS * (H * HD)];
__device__ __half g_qh[(size_t)MROWS * (H * HD)];
__device__ __half g_kh[(size_t)MROWS * (KVH * HD)];
__device__ __half g_kl[(size_t)MROWS * (KVH * HD)];
__device__ __half g_vh[(size_t)MROWS * (KVH * HD)];
__device__ __half g_vl[(size_t)MROWS * (KVH * HD)];

// weight pool layout (elements); QKVW(3072 rows)+A(384 rows) contiguous,
// QB+KB+VB contiguous, OW+OA contiguous.
static constexpr size_t OFF_QKVW = 0;
static constexpr size_t OFF_QB   = 7077888;
static constexpr size_t OFF_OW   = 7471104;
static constexpr size_t OFF_OB   = 11927552;

// ============================================================
// helpers
// ============================================================
__device__ __forceinline__ uint32_t smem_u32(const void* p) {
    uint32_t a;
    asm("{ .reg .u64 t; cvta.to.shared.u64 t, %1; cvt.u32.u64 %0, t; }"
        : "=r"(a) : "l"(p));
    return a;
}
__device__ __forceinline__ void ldm_x4(uint32_t* r, uint32_t addr) {
    asm volatile("ldmatrix.sync.aligned.m8n8.x4.shared.b16 {%0,%1,%2,%3}, [%4];"
                 : "=r"(r[0]), "=r"(r[1]), "=r"(r[2]), "=r"(r[3]) : "r"(addr));
}
__device__ __forceinline__ void ldm_x4_t(uint32_t* r, uint32_t addr) {
    asm volatile("ldmatrix.sync.aligned.m8n8.x4.trans.shared.b16 {%0,%1,%2,%3}, [%4];"
                 : "=r"(r[0]), "=r"(r[1]), "=r"(r[2]), "=r"(r[3]) : "r"(addr));
}
__device__ __forceinline__ void mma16816(float* c, const uint32_t* a, const uint32_t* b) {
    asm volatile(
        "mma.sync.aligned.m16n8k16.row.col.f32.f16.f16.f32 "
        "{%0,%1,%2,%3}, {%4,%5,%6,%7}, {%8,%9}, {%0,%1,%2,%3};"
        : "+f"(c[0]), "+f"(c[1]), "+f"(c[2]), "+f"(c[3])
        : "r"(a[0]), "r"(a[1]), "r"(a[2]), "r"(a[3]), "r"(b[0]), "r"(b[1]));
}
#define CP16(saddr, gptr) \
    asm volatile("cp.async.cg.shared.global [%0], [%1], 16;" :: "r"(saddr), "l"(gptr))
#define CP_COMMIT() asm volatile("cp.async.commit_group;" ::: "memory")
#define CP_WAIT0()  asm volatile("cp.async.wait_group 0;" ::: "memory")
#define CP_WAIT1()  asm volatile("cp.async.wait_group 1;" ::: "memory")

__device__ __forceinline__ uint32_t packh2(float x, float y) {
    __half2 h = __floats2half2_rn(x, y);
    return *(uint32_t*)&h;
}
__device__ __forceinline__ void splith(float x, float y, uint32_t& h, uint32_t& l) {
    __half hx = __float2half_rn(x), hy = __float2half_rn(y);
    __half lx = __float2half_rn(x - __half2float(hx));
    __half ly = __float2half_rn(y - __half2float(hy));
    uint16_t uhx = *(uint16_t*)&hx, uhy = *(uint16_t*)&hy;
    uint16_t ulx = *(uint16_t*)&lx, uly = *(uint16_t*)&ly;
    h = (uint32_t)uhx | ((uint32_t)uhy << 16);
    l = (uint32_t)ulx | ((uint32_t)uly << 16);
}

// ============================================================
// converters
// ============================================================
__global__ void cvtx_kernel(const float* __restrict__ x,
                            __half* __restrict__ hi, int n4)
{
    int i = blockIdx.x * 256 + threadIdx.x;
    if (i >= n4) return;
    float4 v = ((const float4*)x)[i];
    __half h[4] = { __float2half_rn(v.x), __float2half_rn(v.y),
                    __float2half_rn(v.z), __float2half_rn(v.w) };
    *(uint2*)&hi[4*(size_t)i] = *(uint2*)h;
}

__global__ void cvtw_kernel(
    const float* p0, const float* p1, const float* p2, const float* p3,
    const float* p4, const float* p5, const float* p6, const float* p7,
    const float* p8, const float* p9, const float* p10, const float* p11,
    __half* __restrict__ hi, __half* __restrict__ lo)
{
    const float* srcs[12] = {p0,p1,p2,p3,p4,p5,p6,p7,p8,p9,p10,p11};
    const int pre[13] = {0, 1048576, 1114112, 1179648, 1441792, 1507328,
                         1523712, 1785856, 1851392, 1867776, 2916352,
                         2981888, 3047424};
    const int dst[12] = {0, 1572864, 1769472, 1048576, 1638400, 1835008,
                         1310720, 1703936, 1851392, 1867776, 2916352, 2981888};
    int gi = blockIdx.x * 256 + threadIdx.x;
    if (gi >= 3047424) return;
    int s = 0;
#pragma unroll
    for (int t = 1; t < 12; t++) if (gi >= pre[t]) s = t;
    int local = gi - pre[s];
    float4 v = ((const float4*)srcs[s])[local];
    uint32_t h01, l01, h23, l23;
    splith(v.x, v.y, h01, l01);
    splith(v.z, v.w, h23, l23);
    size_t o = 4 * ((size_t)dst[s] + local);
    *(uint32_t*)&hi[o]   = h01; *(uint32_t*)&hi[o+2] = h23;
    *(uint32_t*)&lo[o]   = l01; *(uint32_t*)&lo[o+2] = l23;
}

// ============================================================
// fused RoPE (+scale) + fp16 convert (hi, optional lo)
// ============================================================
__global__ void rope_split_kernel(const float* __restrict__ t,
                                  __half* __restrict__ hi,
                                  __half* __restrict__ lo,
                                  int heads, float scale, int total)
{
    int idx = blockIdx.x * 256 + threadIdx.x;
    if (idx >= total) return;
    int d   = idx & 63;
    int r   = idx >> 6;
    int s   = (r / heads) & (S - 1);
    double invf = pow(1.0e6, -(double)d / 64.0);
    float ang = (float)s * (float)invf;
    float sn, cs;
    sincosf(ang, &sn, &cs);
    const float* p = t + (size_t)r * 128 + 2 * d;
    float xr = p[0], xi = p[1];
    float o0 = (xr * cs - xi * sn) * scale;
    float o1 = (xr * sn + xi * cs) * scale;
    uint32_t hh, ll;
    splith(o0, o1, hh, ll);
    *(uint32_t*)&hi[(size_t)r * 128 + 2 * d] = hh;
    if (lo) *(uint32_t*)&lo[(size_t)r * 128 + 2 * d] = ll;
}

// ============================================================
// mma.sync GEMM, 128x128 CTA tile, 4 warps (64x64), K-chunk 32,
// cp.async double-buffered, 2-pass fp16 (A-hi x (B-hi + B-lo)).
// MODE 1 (QKVA): col<2048->q, <2560->k, <3072->v (fp32); >=3072->th (fp16, ld384)
// MODE 2 (BPROJ): A=th+{0,128,256} by range; accumulate q/k (fp32);
//                 v-range: accumulate then split to vh/vl (ld512)
// MODE 3 (OUT):  col<2048->out (fp32); rest->th (fp16, ld128)
// MODE 4 (ACC):  accumulate into out (fp32)
// ============================================================
template<int MODE>
__global__ void __launch_bounds__(128, 2) gemm_mma(
    const __half* __restrict__ Ahi, const int lda,
    const __half* __restrict__ Bhi, const __half* __restrict__ Blo, const int ldb,
    float* __restrict__ F0, float* __restrict__ F1, float* __restrict__ F2,
    __half* __restrict__ H0, __half* __restrict__ H1,
    const int M, const int N, const int K)
{
    constexpr int BM = 128, BN = 128, WM = 64, WN = 64;
    constexpr int NTHR = 128, MT = WM/16, NT = WN/8, NWN = BN/WN;
    constexpr int ASZ = BM*40, BSZ = BN*40;      // halves
    constexpr int STG = ASZ + 2*BSZ;
    extern __shared__ char dynsm[];
    __half* smem = (__half*)dynsm;

    const int tid = threadIdx.x, lane = tid & 31, warp = tid >> 5;
    const int bm = blockIdx.y * BM;
    const int bn = blockIdx.x * BN;
    const int wm0 = (warp / NWN) * WM, wn0 = (warp % NWN) * WN;
    const uint32_t su = smem_u32(smem);

    // MODE 2: select A column slice by output range
    const __half* Aptr = Ahi;
    if constexpr (MODE == 2)
        Aptr = Ahi + ((bn < 2048) ? 0 : (bn < 2560 ? 128 : 256));

    const int rowA = ((lane >> 3) & 1) * 8 + (lane & 7);
    const int kselA = (lane >> 4) * 8;
    const int rowB = ((lane >> 4) & 1) * 8 + (lane & 7);
    const int kselB = ((lane >> 3) & 1) * 8;

    float acc[MT][NT][4];
#pragma unroll
    for (int i = 0; i < MT; i++)
#pragma unroll
        for (int j = 0; j < NT; j++)
#pragma unroll
            for (int t = 0; t < 4; t++) acc[i][j][t] = 0.f;

    auto load_stage = [&](int st, int k0) {
        uint32_t base = su + (uint32_t)st * STG * 2;
#pragma unroll
        for (int c = tid; c < BM * 4; c += NTHR) {
            int r = c >> 2, sg = c & 3;
            uint32_t so = (uint32_t)(r * 80 + sg * 16);
            size_t ga = (size_t)(bm + r) * lda + k0 + sg * 8;
            CP16(base + so, Aptr + ga);
        }
#pragma unroll
        for (int c = tid; c < BN * 4; c += NTHR) {
            int r = c >> 2, sg = c & 3;
            uint32_t so = (uint32_t)(r * 80 + sg * 16);
            size_t gb = (size_t)(bn + r) * ldb + k0 + sg * 8;
            CP16(base + ASZ * 2 + so, Bhi + gb);
            CP16(base + (ASZ + BSZ) * 2 + so, Blo + gb);
        }
    };

    const int nk = K / 32;
    load_stage(0, 0);
    CP_COMMIT();

    for (int kt = 0; kt < nk; kt++) {
        const int buf = kt & 1;
        if (kt + 1 < nk) {
            load_stage((kt + 1) & 1, (kt + 1) * 32);
            CP_COMMIT();
            CP_WAIT1();
        } else {
            CP_WAIT0();
        }
        __syncthreads();

        const uint32_t uAh = su + (uint32_t)buf * STG * 2;
        const uint32_t uBh = uAh + ASZ * 2;
        const uint32_t uBl = uAh + (ASZ + BSZ) * 2;

#pragma unroll
        for (int kk = 0; kk < 2; kk++) {
            uint32_t ah[MT][4], bh[NT][2], bl[NT][2];
#pragma unroll
            for (int mt = 0; mt < MT; mt++) {
                uint32_t off = (uint32_t)((wm0 + mt*16 + rowA) * 40 + kk*16 + kselA) * 2;
                ldm_x4(ah[mt], uAh + off);
            }
#pragma unroll
            for (int nb = 0; nb < NT / 2; nb++) {
                uint32_t off = (uint32_t)((wn0 + nb*16 + rowB) * 40 + kk*16 + kselB) * 2;
                uint32_t r4[4];
                ldm_x4(r4, uBh + off);
                bh[nb*2][0] = r4[0]; bh[nb*2][1] = r4[1];
                bh[nb*2+1][0] = r4[2]; bh[nb*2+1][1] = r4[3];
                ldm_x4(r4, uBl + off);
                bl[nb*2][0] = r4[0]; bl[nb*2][1] = r4[1];
                bl[nb*2+1][0] = r4[2]; bl[nb*2+1][1] = r4[3];
            }
#pragma unroll
            for (int mt = 0; mt < MT; mt++)
#pragma unroll
                for (int nt = 0; nt < NT; nt++)
                    mma16816(acc[mt][nt], ah[mt], bh[nt]);
#pragma unroll
            for (int mt = 0; mt < MT; mt++)
#pragma unroll
                for (int nt = 0; nt < NT; nt++)
                    mma16816(acc[mt][nt], ah[mt], bl[nt]);
        }
        __syncthreads();
    }

    // ---- epilogue: CTA-uniform routing ----
    const int crow = lane >> 2, ccol = (lane & 3) * 2;
    float* Cf = nullptr;  __half *Sh = nullptr, *Sl = nullptr;
    int ldc = 0, ldcs = 0, col0 = bn;
    bool doAcc = false, doWF = false, doSH = false, doSL = false;

    if constexpr (MODE == 1) {
        if (bn < 2048)      { Cf = F0; ldc = 2048; col0 = bn;        doWF = true; }
        else if (bn < 2560) { Cf = F1; ldc = 512;  col0 = bn - 2048; doWF = true; }
        else if (bn < 3072) { Cf = F2; ldc = 512;  col0 = bn - 2560; doWF = true; }
        else                { Sh = H0; ldcs = 384; col0 = bn - 3072; doSH = true; }
    } else if constexpr (MODE == 2) {
        if (bn < 2048)      { Cf = F0; ldc = 2048; col0 = bn;        doAcc = true; doWF = true; }
        else if (bn < 2560) { Cf = F1; ldc = 512;  col0 = bn - 2048; doAcc = true; doWF = true; }
        else { Cf = F2; ldc = 512; col0 = bn - 2560; doAcc = true;
               Sh = H0; Sl = H1; ldcs = 512; doSH = true; doSL = true; }
    } else if constexpr (MODE == 3) {
        if (bn < 2048)      { Cf = F0; ldc = 2048; col0 = bn;        doWF = true; }
        else                { Sh = H0; ldcs = 128; col0 = bn - 2048; doSH = true; }
    } else {  // MODE 4
        Cf = F0; ldc = 2048; col0 = bn; doAcc = true; doWF = true;
    }

#pragma unroll
    for (int mt = 0; mt < MT; mt++) {
#pragma unroll
        for (int nt = 0; nt < NT; nt++) {
            int r0 = bm + wm0 + mt*16 + crow;
            int c0 = col0 + wn0 + nt*8 + ccol;
            float v00 = acc[mt][nt][0], v01 = acc[mt][nt][1];
            float v10 = acc[mt][nt][2], v11 = acc[mt][nt][3];
            if (doAcc) {
                float2 o0 = *(float2*)&Cf[(size_t)r0 * ldc + c0];
                float2 o1 = *(float2*)&Cf[(size_t)(r0+8) * ldc + c0];
                v00 += o0.x; v01 += o0.y; v10 += o1.x; v11 += o1.y;
            }
            if (doWF) {
                *(float2*)&Cf[(size_t)r0 * ldc + c0]     = make_float2(v00, v01);
                *(float2*)&Cf[(size_t)(r0+8) * ldc + c0] = make_float2(v10, v11);
            }
            if (doSH) {
                uint32_t hh, ll;
                splith(v00, v01, hh, ll);
                *(uint32_t*)&Sh[(size_t)r0 * ldcs + c0] = hh;
                if (doSL) *(uint32_t*)&Sl[(size_t)r0 * ldcs + c0] = ll;
                splith(v10, v11, hh, ll);
                *(uint32_t*)&Sh[(size_t)(r0+8) * ldcs + c0] = hh;
                if (doSL) *(uint32_t*)&Sl[(size_t)(r0+8) * ldcs + c0] = ll;
            }
        }
    }
}

// ============================================================
// Tensor-core flash attention, 2-pass fp16, cp.async K/V pipeline.
// CTA: 128 q rows x head x batch; 8 warps x 16 rows; 64-key blocks.
// ============================================================
static constexpr int AQ_H = 0;          // 128*136 halves
static constexpr int ASTG = 34816;
static constexpr int AKL = 8704, AVH = 17408, AVL = 26112;
static constexpr int ATTN_SMEM_BYTES = (17408 + 2 * ASTG) * 2;  // 174080

__global__ void __launch_bounds__(256) attn_mma_kernel(
    const __half* __restrict__ qh,
    const __half* __restrict__ kh, const __half* __restrict__ kl,
    const __half* __restrict__ vh, const __half* __restrict__ vl,
    __half* __restrict__ aoh)
{
    extern __shared__ char dynsm[];
    __half* sm = (__half*)dynsm;
    const int qb = blockIdx.x, h = blockIdx.y, b = blockIdx.z;
    const int i0 = qb * 128;
    const int tid = threadIdx.x, lane = tid & 31, warp = tid >> 5;
    const int kvh = h >> 2;
    const uint32_t su = smem_u32(sm);

#pragma unroll
    for (int c = tid; c < 128 * 16; c += 256) {
        int r = c >> 4, sg = c & 15;
        size_t g = ((size_t)(b*S + i0 + r)) * (H*HD) + h*HD + sg*8;
        *(uint4*)&sm[AQ_H + r*136 + sg*8] = *(const uint4*)(qh + g);
    }

    float O[16][4];
#pragma unroll
    for (int i = 0; i < 16; i++)
#pragma unroll
        for (int t = 0; t < 4; t++) O[i][t] = 0.f;
    float m0 = -1e30f, m1 = -1e30f, l0 = 0.f, l1 = 0.f;

    const int rowA = ((lane >> 3) & 1) * 8 + (lane & 7);
    const int kselA = (lane >> 4) * 8;
    const int rowB = ((lane >> 4) & 1) * 8 + (lane & 7);
    const int kselB = ((lane >> 3) & 1) * 8;
    const int rowV = ((lane >> 3) & 1) * 8 + (lane & 7);
    const int colV = (lane >> 4) * 8;

    int startb = 2*qb - 8; if (startb < 1) startb = 1;
    const int kb_end = 2*qb + 1;
    const int nblk = 1 + (kb_end - startb + 1);

    const int ir0 = i0 + warp*16 + (lane >> 2);
    const int ir1 = ir0 + 8;

    auto kbof = [&](int i) { return (i == 0) ? 0 : (startb + i - 1); };
    auto load_kv = [&](int st, int kb) {
        uint32_t base = su + (uint32_t)(17408 + ASTG * st) * 2;
#pragma unroll
        for (int c = tid; c < 64 * 16; c += 256) {
            int r = c >> 4, sg = c & 15;
            size_t g = ((size_t)(b*S + kb*64 + r)) * (KVH*HD) + kvh*HD + sg*8;
            uint32_t so = (uint32_t)(r*136 + sg*8) * 2;
            CP16(base + so, kh + g);
            CP16(base + AKL*2 + so, kl + g);
            CP16(base + AVH*2 + so, vh + g);
            CP16(base + AVL*2 + so, vl + g);
        }
    };

    load_kv(0, kbof(0));
    CP_COMMIT();
    if (nblk > 1) { load_kv(1, kbof(1)); CP_COMMIT(); }

    for (int bi = 0; bi < nblk; bi++) {
        if (bi + 1 < nblk) CP_WAIT1(); else CP_WAIT0();
        __syncthreads();
        const int kb = kbof(bi);
        const uint32_t sb2 = su + (uint32_t)(17408 + ASTG * (bi & 1)) * 2;

        float sc[8][4];
#pragma unroll
        for (int i = 0; i < 8; i++)
#pragma unroll
            for (int t = 0; t < 4; t++) sc[i][t] = 0.f;

#pragma unroll
        for (int kk = 0; kk < 8; kk++) {
            uint32_t ah[4];
            uint32_t offA = (uint32_t)((warp*16 + rowA)*136 + kk*16 + kselA) * 2;
            ldm_x4(ah, su + AQ_H*2 + offA);
#pragma unroll
            for (int g2 = 0; g2 < 4; g2++) {
                uint32_t bh4[4], bl4[4];
                uint32_t offB = (uint32_t)((g2*16 + rowB)*136 + kk*16 + kselB) * 2;
                ldm_x4(bh4, sb2 + offB);
                ldm_x4(bl4, sb2 + AKL*2 + offB);
                mma16816(sc[2*g2],   ah, bh4);
                mma16816(sc[2*g2+1], ah, bh4 + 2);
                mma16816(sc[2*g2],   ah, bl4);
                mma16816(sc[2*g2+1], ah, bl4 + 2);
            }
        }

        const int jb = kb*64 + (lane & 3) * 2;
        float mx0 = -1e30f, mx1 = -1e30f;
#pragma unroll
        for (int nt = 0; nt < 8; nt++) {
            int j0 = jb + nt*8, j1 = j0 + 1;
            if (!((j0 <= ir0) && (((ir0 - j0) < WINDOW) || (j0 < GLOBALK)))) sc[nt][0] = -1e30f;
            if (!((j1 <= ir0) && (((ir0 - j1) < WINDOW) || (j1 < GLOBALK)))) sc[nt][1] = -1e30f;
            if (!((j0 <= ir1) && (((ir1 - j0) < WINDOW) || (j0 < GLOBALK)))) sc[nt][2] = -1e30f;
            if (!((j1 <= ir1) && (((ir1 - j1) < WINDOW) || (j1 < GLOBALK)))) sc[nt][3] = -1e30f;
            mx0 = fmaxf(mx0, fmaxf(sc[nt][0], sc[nt][1]));
            mx1 = fmaxf(mx1, fmaxf(sc[nt][2], sc[nt][3]));
        }
        mx0 = fmaxf(mx0, __shfl_xor_sync(0xffffffffu, mx0, 1));
        mx0 = fmaxf(mx0, __shfl_xor_sync(0xffffffffu, mx0, 2));
        mx1 = fmaxf(mx1, __shfl_xor_sync(0xffffffffu, mx1, 1));
        mx1 = fmaxf(mx1, __shfl_xor_sync(0xffffffffu, mx1, 2));

        float nm0 = fmaxf(m0, mx0), nm1 = fmaxf(m1, mx1);
        float a0 = __expf(m0 - nm0), a1 = __expf(m1 - nm1);
        float s0 = 0.f, s1 = 0.f;
#pragma unroll
        for (int nt = 0; nt < 8; nt++) {
            sc[nt][0] = __expf(sc[nt][0] - nm0);
            sc[nt][1] = __expf(sc[nt][1] - nm0);
            sc[nt][2] = __expf(sc[nt][2] - nm1);
            sc[nt][3] = __expf(sc[nt][3] - nm1);
            s0 += sc[nt][0] + sc[nt][1];
            s1 += sc[nt][2] + sc[nt][3];
        }
        s0 += __shfl_xor_sync(0xffffffffu, s0, 1);
        s0 += __shfl_xor_sync(0xffffffffu, s0, 2);
        s1 += __shfl_xor_sync(0xffffffffu, s1, 1);
        s1 += __shfl_xor_sync(0xffffffffu, s1, 2);
        l0 = l0 * a0 + s0;  l1 = l1 * a1 + s1;
        m0 = nm0;  m1 = nm1;
#pragma unroll
        for (int dt = 0; dt < 16; dt++) {
            O[dt][0] *= a0; O[dt][1] *= a0;
            O[dt][2] *= a1; O[dt][3] *= a1;
        }

#pragma unroll
        for (int kk = 0; kk < 4; kk++) {
            uint32_t pah[4];
            pah[0] = packh2(sc[2*kk][0],   sc[2*kk][1]);
            pah[1] = packh2(sc[2*kk][2],   sc[2*kk][3]);
            pah[2] = packh2(sc[2*kk+1][0], sc[2*kk+1][1]);
            pah[3] = packh2(sc[2*kk+1][2], sc[2*kk+1][3]);
#pragma unroll
            for (int dt2 = 0; dt2 < 8; dt2++) {
                uint32_t vbh[4], vbl[4];
                uint32_t offV = (uint32_t)((kk*16 + rowV)*136 + dt2*16 + colV) * 2;
                ldm_x4_t(vbh, sb2 + AVH*2 + offV);
                ldm_x4_t(vbl, sb2 + AVL*2 + offV);
                mma16816(O[2*dt2],   pah, vbh);
                mma16816(O[2*dt2+1], pah, vbh + 2);
                mma16816(O[2*dt2],   pah, vbl);
                mma16816(O[2*dt2+1], pah, vbl + 2);
            }
        }

        __syncthreads();
        if (bi + 2 < nblk) { load_kv(bi & 1, kbof(bi + 2)); CP_COMMIT(); }
    }

    const float inv0 = 1.f / l0, inv1 = 1.f / l1;
    const size_t rbase0 = ((size_t)(b*S + i0 + warp*16 + (lane >> 2))) * (H*HD);
    const size_t rbase1 = rbase0 + 8 * (size_t)(H*HD);
#pragma unroll
    for (int dt = 0; dt < 16; dt++) {
        int cc = h*HD + dt*8 + (lane & 3) * 2;
        *(uint32_t*)&aoh[rbase0 + cc] = packh2(O[dt][0]*inv0, O[dt][1]*inv0);
        *(uint32_t*)&aoh[rbase1 + cc] = packh2(O[dt][2]*inv1, O[dt][3]*inv1);
    }
}

// ============================================================
// Host side
// ============================================================
static constexpr int SMEM_G128 = 2 * (128*40 + 2*128*40) * 2;   // 61440

extern "C" void kernel_launch(void* const* d_in, const int* in_sizes, int n_in,
                              void* d_out, int out_size)
{
    const float* x = (const float*)d_in[0];
    float* out = (float*)d_out;

    float *q, *k, *v;
    __half *xh, *wh, *wl, *th, *aoh, *qhp, *khp, *klp, *vhp, *vlp;
    cudaGetSymbolAddress((void**)&q,   g_q);
    cudaGetSymbolAddress((void**)&k,   g_k);
    cudaGetSymbolAddress((void**)&v,   g_v);
    cudaGetSymbolAddress((void**)&xh,  g_xh);
    cudaGetSymbolAddress((void**)&wh,  g_wh);
    cudaGetSymbolAddress((void**)&wl,  g_wl);
    cudaGetSymbolAddress((void**)&th,  g_th);
    cudaGetSymbolAddress((void**)&aoh, g_aoh);
    cudaGetSymbolAddress((void**)&qhp, g_qh);
    cudaGetSymbolAddress((void**)&khp, g_kh);
    cudaGetSymbolAddress((void**)&klp, g_kl);
    cudaGetSymbolAddress((void**)&vhp, g_vh);
    cudaGetSymbolAddress((void**)&vlp, g_vl);

    cudaFuncSetAttribute(gemm_mma<1>, cudaFuncAttributeMaxDynamicSharedMemorySize, SMEM_G128);
    cudaFuncSetAttribute(gemm_mma<2>, cudaFuncAttributeMaxDynamicSharedMemorySize, SMEM_G128);
    cudaFuncSetAttribute(gemm_mma<3>, cudaFuncAttributeMaxDynamicSharedMemorySize, SMEM_G128);
    cudaFuncSetAttribute(gemm_mma<4>, cudaFuncAttributeMaxDynamicSharedMemorySize, SMEM_G128);
    cudaFuncSetAttribute(attn_mma_kernel,
        cudaFuncAttributeMaxDynamicSharedMemorySize, ATTN_SMEM_BYTES);

    const int M = MROWS;

    // ---- converts ----
    cvtx_kernel<<<(M*D/4 + 255)/256, 256>>>(x, xh, M*D/4);
    cvtw_kernel<<<(3047424 + 255)/256, 256>>>(
        (const float*)d_in[1], (const float*)d_in[2], (const float*)d_in[3],
        (const float*)d_in[4], (const float*)d_in[5], (const float*)d_in[6],
        (const float*)d_in[7], (const float*)d_in[8], (const float*)d_in[9],
        (const float*)d_in[10], (const float*)d_in[11], (const float*)d_in[12],
        wh, wl);

    // ---- G1: q|k|v|th = x @ [wq_w; wk_w; wv_w; wq_a; wk_a; wv_a]^T ----
    gemm_mma<1><<<dim3(3456/128, 32), 128, SMEM_G128>>>(
        xh, D, wh+OFF_QKVW, wl+OFF_QKVW, D,
        q, k, v, th, nullptr, M, 3456, D);

    // ---- G2: fused LoRA b-projections (accumulate; v-range splits) ----
    gemm_mma<2><<<dim3(3072/128, 32), 128, SMEM_G128>>>(
        th, 384, wh+OFF_QB, wl+OFF_QB, 128,
        q, k, v, vhp, vlp, M, 3072, 128);

    // ---- RoPE + fp16 convert ----
    {
        int tq = M * H * 64;
        rope_split_kernel<<<(tq + 255)/256, 256>>>(q, qhp, nullptr, H, SCALE, tq);
        int tk = M * KVH * 64;
        rope_split_kernel<<<(tk + 255)/256, 256>>>(k, khp, klp, KVH, 1.0f, tk);
    }

    // ---- attention ----
    {
        dim3 grid(S/128, H, B);
        attn_mma_kernel<<<grid, 256, ATTN_SMEM_BYTES>>>(
            qhp, khp, klp, vhp, vlp, aoh);
    }

    // ---- G3: out|th = ao @ [wo_w; wo_a]^T ----
    gemm_mma<3><<<dim3(2176/128, 32), 128, SMEM_G128>>>(
        aoh, 2048, wh+OFF_OW, wl+OFF_OW, 2048,
        out, nullptr, nullptr, th, nullptr, M, 2176, 2048);

    // ---- G4: out += th @ wo_b^T ----
    gemm_mma<4><<<dim3(2048/128, 32), 128, SMEM_G128>>>(
        th, 128, wh+OFF_OB, wl+OFF_OB, 128,
        out, nullptr, nullptr, nullptr, nullptr, M, 2048, 128);
}